// round 1
// baseline (speedup 1.0000x reference)
#include <cuda_runtime.h>
#include <math.h>

#define T_SEQ 4096
#define DIM   2048
#define NH    16
#define HD    128

// ---------------- scratch (no allocations allowed) ----------------
__device__ float g_q[T_SEQ * DIM];
__device__ float g_k[T_SEQ * DIM];
__device__ float g_v[T_SEQ * DIM];
__device__ float g_o[T_SEQ * DIM];

// ---------------- GEMM: C[M,N] = A[M,K] @ W[K,N] + bias ----------------
// M=4096, N=2048, K=2048. 128x128 block tile, BK=8, 256 threads, 8x8 microtile.
__global__ __launch_bounds__(256) void sgemm_bias(const float* __restrict__ A,
                                                  const float* __restrict__ W,
                                                  const float* __restrict__ bias,
                                                  float* __restrict__ C)
{
    const int M = 4096, N = 2048, K = 2048;
    (void)M;
    __shared__ float As[8][128];
    __shared__ float Bs[8][128];

    const int tid  = threadIdx.x;
    const int row0 = blockIdx.y * 128;
    const int col0 = blockIdx.x * 128;
    const int ty   = tid >> 4;   // 0..15
    const int tx   = tid & 15;   // 0..15

    // load mapping
    const int arow  = tid >> 1;          // 0..127
    const int acol4 = (tid & 1) * 4;     // 0 or 4
    const int brow  = tid >> 5;          // 0..7
    const int bcol4 = (tid & 31) * 4;    // 0..124

    const float* Aptr = A + (size_t)(row0 + arow) * K + acol4;
    const float* Wptr = W + (size_t)brow * N + col0 + bcol4;

    float acc[8][8];
#pragma unroll
    for (int i = 0; i < 8; i++)
#pragma unroll
        for (int j = 0; j < 8; j++) acc[i][j] = 0.f;

    for (int k0 = 0; k0 < K; k0 += 8) {
        float4 av = *(const float4*)(Aptr + k0);
        float4 wv = *(const float4*)(Wptr + (size_t)k0 * N);
        As[acol4 + 0][arow] = av.x;
        As[acol4 + 1][arow] = av.y;
        As[acol4 + 2][arow] = av.z;
        As[acol4 + 3][arow] = av.w;
        *(float4*)&Bs[brow][bcol4] = wv;
        __syncthreads();

#pragma unroll
        for (int kk = 0; kk < 8; kk++) {
            float a[8], b[8];
#pragma unroll
            for (int i = 0; i < 8; i++) a[i] = As[kk][ty * 8 + i];
#pragma unroll
            for (int j = 0; j < 8; j++) b[j] = Bs[kk][tx * 8 + j];
#pragma unroll
            for (int i = 0; i < 8; i++)
#pragma unroll
                for (int j = 0; j < 8; j++)
                    acc[i][j] += a[i] * b[j];
        }
        __syncthreads();
    }

    // epilogue with bias
    float4 b0 = *(const float4*)(bias + col0 + tx * 8);
    float4 b1 = *(const float4*)(bias + col0 + tx * 8 + 4);
#pragma unroll
    for (int i = 0; i < 8; i++) {
        float* cp = C + (size_t)(row0 + ty * 8 + i) * N + col0 + tx * 8;
        float4 v0, v1;
        v0.x = acc[i][0] + b0.x; v0.y = acc[i][1] + b0.y;
        v0.z = acc[i][2] + b0.z; v0.w = acc[i][3] + b0.w;
        v1.x = acc[i][4] + b1.x; v1.y = acc[i][5] + b1.y;
        v1.z = acc[i][6] + b1.z; v1.w = acc[i][7] + b1.w;
        *(float4*)cp       = v0;
        *(float4*)(cp + 4) = v1;
    }
}

// ---------------- RMSNorm (over DIM) + RoPE (per-head pairs) ----------------
__global__ __launch_bounds__(256) void rmsnorm_rope(float* __restrict__ buf,
                                                    const float* __restrict__ g,
                                                    const float* __restrict__ freqs)
{
    const int t = blockIdx.x;
    float* row = buf + (size_t)t * DIM;

    float ss = 0.f;
    for (int i = threadIdx.x; i < DIM; i += 256) {
        float v = row[i];
        ss += v * v;
    }
#pragma unroll
    for (int off = 16; off; off >>= 1) ss += __shfl_xor_sync(0xFFFFFFFFu, ss, off);

    __shared__ float red[8];
    __shared__ float stot;
    if ((threadIdx.x & 31) == 0) red[threadIdx.x >> 5] = ss;
    __syncthreads();
    if (threadIdx.x == 0) {
        float tot = 0.f;
#pragma unroll
        for (int i = 0; i < 8; i++) tot += red[i];
        stot = tot;
    }
    __syncthreads();

    const float scale = rsqrtf(stot * (1.f / DIM) + 1e-6f);

    for (int p = threadIdx.x; p < DIM / 2; p += 256) {
        int e   = 2 * p;
        int pin = p & 63;  // pair index within head (HD/2 = 64)
        float ang = freqs[(size_t)t * 64 + pin];
        float c, s;
        // accurate range reduction needed: angles up to ~4095 rad
        sincosf(ang, &s, &c);
        float x0 = row[e]     * scale * g[e];
        float x1 = row[e + 1] * scale * g[e + 1];
        row[e]     = x0 * c - x1 * s;
        row[e + 1] = x0 * s + x1 * c;
    }
}

// ---------------- causal flash attention (fp32) ----------------
// grid: (T/64 q-tiles, H heads). 256 threads. 64-query x 64-key tiles, HD=128.
__global__ __launch_bounds__(256) void flash_attn(const float* __restrict__ Q,
                                                  const float* __restrict__ K,
                                                  const float* __restrict__ V,
                                                  float* __restrict__ O)
{
    extern __shared__ float sm[];
    float* Qs   = sm;              // [128][65]  : Qs[i*65 + r]  (dim-major)
    float* KVs  = Qs + 128 * 65;   // K phase: [128][65] dim-major ; V phase: [64][128] row-major
    float* Ss   = KVs + 128 * 65;  // [64][65]
    float* mnew = Ss + 64 * 65;    // [64]
    float* fac  = mnew + 64;       // [64]
    float* lsh  = fac + 64;        // [64]

    const int qt = blockIdx.x;
    const int h  = blockIdx.y;
    const int q0 = qt * 64;
    const int tid = threadIdx.x;
    const int tr = tid >> 4;  // 0..15 -> q rows 4*tr..4*tr+3
    const int tc = tid & 15;  // 0..15 -> S cols 4*tc.. / dims 8*tc..
    const float scale = 0.08838834764831845f;  // 1/sqrt(128)

    // load Q tile (dim-major, stride 65 -> conflict free)
    for (int idx = tid; idx < 64 * 128; idx += 256) {
        int r = idx >> 7, i = idx & 127;
        Qs[i * 65 + r] = Q[(size_t)(q0 + r) * DIM + h * HD + i];
    }

    float o[4][8];
#pragma unroll
    for (int a = 0; a < 4; a++)
#pragma unroll
        for (int d = 0; d < 8; d++) o[a][d] = 0.f;

    float mrow = -INFINITY;  // valid only for tid < 64
    float lrow = 0.f;

    for (int j = 0; j <= qt; j++) {
        // ---- load K tile (dim-major) ----
        for (int idx = tid; idx < 64 * 128; idx += 256) {
            int c = idx >> 7, i = idx & 127;
            KVs[i * 65 + c] = K[(size_t)(j * 64 + c) * DIM + h * HD + i];
        }
        __syncthreads();

        // ---- S = Q K^T (4x4 microtile per thread) ----
        float acc[4][4];
#pragma unroll
        for (int a = 0; a < 4; a++)
#pragma unroll
            for (int b = 0; b < 4; b++) acc[a][b] = 0.f;

#pragma unroll 4
        for (int i = 0; i < 128; i++) {
            float qv[4], kv[4];
#pragma unroll
            for (int a = 0; a < 4; a++) qv[a] = Qs[i * 65 + 4 * tr + a];
#pragma unroll
            for (int b = 0; b < 4; b++) kv[b] = KVs[i * 65 + 4 * tc + b];
#pragma unroll
            for (int a = 0; a < 4; a++)
#pragma unroll
                for (int b = 0; b < 4; b++) acc[a][b] += qv[a] * kv[b];
        }

        const bool diag = (j == qt);
#pragma unroll
        for (int a = 0; a < 4; a++)
#pragma unroll
            for (int b = 0; b < 4; b++) {
                float s = acc[a][b] * scale;
                if (diag && (4 * tc + b) > (4 * tr + a)) s = -1e30f;
                Ss[(4 * tr + a) * 65 + 4 * tc + b] = s;
            }
        __syncthreads();

        // ---- per-row max / rescale factor (threads 0..63 own one row each) ----
        if (tid < 64) {
            float mx = -1e30f;
#pragma unroll 8
            for (int c = 0; c < 64; c++) mx = fmaxf(mx, Ss[tid * 65 + c]);
            float mn = fmaxf(mrow, mx);
            fac[tid]  = (mrow == -INFINITY) ? 0.f : __expf(mrow - mn);
            mnew[tid] = mn;
            mrow = mn;
        }
        __syncthreads();

        // ---- P = exp(S - m) (all threads), V load (all threads) ----
        for (int idx = tid; idx < 64 * 64; idx += 256) {
            int r = idx >> 6, c = idx & 63;
            Ss[r * 65 + c] = __expf(Ss[r * 65 + c] - mnew[r]);
        }
        for (int idx = tid; idx < 64 * 128; idx += 256) {
            int k = idx >> 7, d = idx & 127;
            KVs[k * 128 + d] = V[(size_t)(j * 64 + k) * DIM + h * HD + d];
        }
        // rescale O accumulators (fac valid since previous sync)
        {
            float f[4];
#pragma unroll
            for (int a = 0; a < 4; a++) f[a] = fac[4 * tr + a];
#pragma unroll
            for (int a = 0; a < 4; a++)
#pragma unroll
                for (int d = 0; d < 8; d++) o[a][d] *= f[a];
        }
        __syncthreads();

        // ---- l update ----
        if (tid < 64) {
            float rs = 0.f;
#pragma unroll 8
            for (int c = 0; c < 64; c++) rs += Ss[tid * 65 + c];
            lrow = lrow * fac[tid] + rs;
        }

        // ---- O += P V (4 rows x 8 dims per thread) ----
#pragma unroll 4
        for (int k = 0; k < 64; k++) {
            float pv[4], vv[8];
#pragma unroll
            for (int a = 0; a < 4; a++) pv[a] = Ss[(4 * tr + a) * 65 + k];
#pragma unroll
            for (int d = 0; d < 8; d++) vv[d] = KVs[k * 128 + tc * 8 + d];
#pragma unroll
            for (int a = 0; a < 4; a++)
#pragma unroll
                for (int d = 0; d < 8; d++) o[a][d] += pv[a] * vv[d];
        }
        __syncthreads();
    }

    if (tid < 64) lsh[tid] = lrow;
    __syncthreads();

#pragma unroll
    for (int a = 0; a < 4; a++) {
        float inv = 1.f / lsh[4 * tr + a];
        float* op = O + (size_t)(q0 + 4 * tr + a) * DIM + h * HD + tc * 8;
        float4 v0, v1;
        v0.x = o[a][0] * inv; v0.y = o[a][1] * inv;
        v0.z = o[a][2] * inv; v0.w = o[a][3] * inv;
        v1.x = o[a][4] * inv; v1.y = o[a][5] * inv;
        v1.z = o[a][6] * inv; v1.w = o[a][7] * inv;
        *(float4*)op       = v0;
        *(float4*)(op + 4) = v1;
    }
}

// ---------------- launch ----------------
extern "C" void kernel_launch(void* const* d_in, const int* in_sizes, int n_in,
                              void* d_out, int out_size)
{
    (void)in_sizes; (void)n_in; (void)out_size;
    const float* x     = (const float*)d_in[0];
    const float* freqs = (const float*)d_in[1];
    const float* Wq    = (const float*)d_in[2];
    const float* bq    = (const float*)d_in[3];
    const float* Wk    = (const float*)d_in[4];
    const float* bk    = (const float*)d_in[5];
    const float* Wv    = (const float*)d_in[6];
    const float* bv    = (const float*)d_in[7];
    const float* Wo    = (const float*)d_in[8];
    const float* bo    = (const float*)d_in[9];
    const float* gq    = (const float*)d_in[10];
    const float* gk    = (const float*)d_in[11];

    float *q, *k, *v, *o;
    cudaGetSymbolAddress((void**)&q, g_q);
    cudaGetSymbolAddress((void**)&k, g_k);
    cudaGetSymbolAddress((void**)&v, g_v);
    cudaGetSymbolAddress((void**)&o, g_o);

    dim3 ggrid(DIM / 128, T_SEQ / 128);  // (16, 32)
    sgemm_bias<<<ggrid, 256>>>(x, Wq, bq, q);
    sgemm_bias<<<ggrid, 256>>>(x, Wk, bk, k);
    sgemm_bias<<<ggrid, 256>>>(x, Wv, bv, v);

    rmsnorm_rope<<<T_SEQ, 256>>>(q, gq, freqs);
    rmsnorm_rope<<<T_SEQ, 256>>>(k, gk, freqs);

    const int smem_bytes = (128 * 65 + 128 * 65 + 64 * 65 + 3 * 64) * (int)sizeof(float);
    cudaFuncSetAttribute(flash_attn, cudaFuncAttributeMaxDynamicSharedMemorySize, smem_bytes);
    dim3 agrid(T_SEQ / 64, NH);  // (64, 16)
    flash_attn<<<agrid, 256, smem_bytes>>>(q, k, v, o);

    sgemm_bias<<<ggrid, 256>>>(o, Wo, bo, (float*)d_out);
}

// round 4
// speedup vs baseline: 1.5352x; 1.5352x over previous
#include <cuda_runtime.h>
#include <math.h>
#include <stdint.h>

#define T_SEQ 4096
#define DIM   2048
#define NH    16
#define HD    128
#define GK    2048

// ---------------- scratch (no allocations allowed) ----------------
__device__ float g_q[T_SEQ * DIM];
__device__ float g_k[T_SEQ * DIM];
__device__ float g_v[T_SEQ * DIM];
__device__ float g_o[T_SEQ * DIM];

// =================== helpers ===================
__device__ __forceinline__ uint32_t smem_u32(const void* p) {
    uint32_t a;
    asm("{ .reg .u64 t; cvta.to.shared.u64 t, %1; cvt.u32.u64 %0, t; }" : "=r"(a) : "l"(p));
    return a;
}
__device__ __forceinline__ uint32_t tf32b(float x) {
    uint32_t r;
    asm("cvt.rna.tf32.f32 %0, %1;" : "=r"(r) : "f"(x));
    return r;
}
__device__ __forceinline__ void cpa16(uint32_t saddr, const void* g) {
    asm volatile("cp.async.cg.shared.global [%0], [%1], 16;" :: "r"(saddr), "l"(g));
}
__device__ __forceinline__ void mma8(float* d, const uint32_t* a, uint32_t b0, uint32_t b1) {
    asm volatile(
        "mma.sync.aligned.m16n8k8.row.col.f32.tf32.tf32.f32 "
        "{%0,%1,%2,%3}, {%4,%5,%6,%7}, {%8,%9}, {%0,%1,%2,%3};"
        : "+f"(d[0]), "+f"(d[1]), "+f"(d[2]), "+f"(d[3])
        : "r"(a[0]), "r"(a[1]), "r"(a[2]), "r"(a[3]), "r"(b0), "r"(b1));
}

// =================== mma.sync tf32 GEMM ===================
// C[M,N] = A[M,K] @ W[K,N] + bias.  CTA tile 128x128, BK=16, 3-stage cp.async.
// 8 warps: (wid>>1) -> 32-row band, (wid&1) -> 64-col band. Warp = 32x64 (2x8 mma tiles).
#define BK        16
#define NSTG      3
#define A_ROWB    80                 // 20 floats per A row (16 + 4 pad)
#define B_ROWB    544                // 136 floats per B row (128 + 8 pad)
#define A_BYTES   (128 * A_ROWB)     // 10240
#define B_BYTES   (BK * B_ROWB)      // 8704
#define STG_BYTES (A_BYTES + B_BYTES)
#define NT        (GK / BK)          // 128 k-tiles

__device__ __forceinline__ void load_stage(uint32_t sb, const float* __restrict__ A,
                                           const float* __restrict__ W,
                                           int m0, int n0, int kt, int tid) {
    uint32_t st = sb + (uint32_t)(kt % NSTG) * STG_BYTES;
    const int k0 = kt * BK;
#pragma unroll
    for (int i = 0; i < 2; i++) {
        int id = tid + i * 256;            // 0..511
        int row = id >> 2, seg = id & 3;   // A: 128 rows x 4 chunks
        cpa16(st + row * A_ROWB + seg * 16,
              A + (size_t)(m0 + row) * GK + k0 + seg * 4);
    }
#pragma unroll
    for (int i = 0; i < 2; i++) {
        int id = tid + i * 256;            // 0..511
        int kr = id >> 5, seg = id & 31;   // B: 16 rows x 32 chunks
        cpa16(st + A_BYTES + kr * B_ROWB + seg * 16,
              W + (size_t)(k0 + kr) * DIM + n0 + seg * 4);
    }
}

__global__ __launch_bounds__(256) void gemm_mma(const float* __restrict__ A,
                                                const float* __restrict__ W,
                                                const float* __restrict__ bias,
                                                float* __restrict__ C)
{
    extern __shared__ __align__(16) char smem[];
    const uint32_t sb = smem_u32(smem);
    const int tid  = threadIdx.x;
    const int lane = tid & 31;
    const int wid  = tid >> 5;
    const int wm   = (wid >> 1) * 32;
    const int wn   = (wid & 1) * 64;
    const int n0   = blockIdx.x * 128;
    const int m0   = blockIdx.y * 128;

    const int gq = lane >> 2;   // group id 0..7
    const int tg = lane & 3;    // thread-in-group 0..3

    float acc[2][8][4];
#pragma unroll
    for (int mi = 0; mi < 2; mi++)
#pragma unroll
        for (int ni = 0; ni < 8; ni++)
#pragma unroll
            for (int r = 0; r < 4; r++) acc[mi][ni][r] = 0.f;

    // prologue: stages 0..2
#pragma unroll
    for (int kt = 0; kt < NSTG; kt++) {
        load_stage(sb, A, W, m0, n0, kt, tid);
        asm volatile("cp.async.commit_group;" ::: "memory");
    }

    for (int kt = 0; kt < NT; kt++) {
        asm volatile("cp.async.wait_group %0;" :: "n"(NSTG - 1) : "memory");
        __syncthreads();

        const float* smf = (const float*)(smem + (kt % NSTG) * STG_BYTES);
        const float* bsf = (const float*)(smem + (kt % NSTG) * STG_BYTES + A_BYTES);

#pragma unroll
        for (int ks = 0; ks < BK; ks += 8) {
            uint32_t afr[2][4];
#pragma unroll
            for (int mi = 0; mi < 2; mi++) {
                int r0 = wm + mi * 16 + gq;
                int c0 = ks + tg;
                afr[mi][0] = tf32b(smf[r0 * 20 + c0]);
                afr[mi][1] = tf32b(smf[(r0 + 8) * 20 + c0]);
                afr[mi][2] = tf32b(smf[r0 * 20 + c0 + 4]);
                afr[mi][3] = tf32b(smf[(r0 + 8) * 20 + c0 + 4]);
            }
#pragma unroll
            for (int ni = 0; ni < 8; ni++) {
                int nb = wn + ni * 8 + gq;
                uint32_t b0 = tf32b(bsf[(ks + tg) * 136 + nb]);
                uint32_t b1 = tf32b(bsf[(ks + tg + 4) * 136 + nb]);
                mma8(acc[0][ni], afr[0], b0, b1);
                mma8(acc[1][ni], afr[1], b0, b1);
            }
        }
        __syncthreads();

        if (kt + NSTG < NT)
            load_stage(sb, A, W, m0, n0, kt + NSTG, tid);
        asm volatile("cp.async.commit_group;" ::: "memory");
    }

    // epilogue
#pragma unroll
    for (int mi = 0; mi < 2; mi++) {
        int row = m0 + wm + mi * 16 + gq;
#pragma unroll
        for (int ni = 0; ni < 8; ni++) {
            int col = n0 + wn + ni * 8 + 2 * tg;
            float2 bz = *(const float2*)(bias + col);
            float2 v0, v1;
            v0.x = acc[mi][ni][0] + bz.x; v0.y = acc[mi][ni][1] + bz.y;
            v1.x = acc[mi][ni][2] + bz.x; v1.y = acc[mi][ni][3] + bz.y;
            *(float2*)(C + (size_t)row * DIM + col)       = v0;
            *(float2*)(C + (size_t)(row + 8) * DIM + col) = v1;
        }
    }
}

// ---------------- RMSNorm (over DIM) + RoPE (per-head pairs) ----------------
__global__ __launch_bounds__(256) void rmsnorm_rope(float* __restrict__ buf,
                                                    const float* __restrict__ g,
                                                    const float* __restrict__ freqs)
{
    const int t = blockIdx.x;
    float* row = buf + (size_t)t * DIM;

    float ss = 0.f;
    for (int i = threadIdx.x; i < DIM; i += 256) {
        float v = row[i];
        ss += v * v;
    }
#pragma unroll
    for (int off = 16; off; off >>= 1) ss += __shfl_xor_sync(0xFFFFFFFFu, ss, off);

    __shared__ float red[8];
    __shared__ float stot;
    if ((threadIdx.x & 31) == 0) red[threadIdx.x >> 5] = ss;
    __syncthreads();
    if (threadIdx.x == 0) {
        float tot = 0.f;
#pragma unroll
        for (int i = 0; i < 8; i++) tot += red[i];
        stot = tot;
    }
    __syncthreads();

    const float scale = rsqrtf(stot * (1.f / DIM) + 1e-6f);

    for (int p = threadIdx.x; p < DIM / 2; p += 256) {
        int e   = 2 * p;
        int pin = p & 63;
        float ang = freqs[(size_t)t * 64 + pin];
        float c, s;
        sincosf(ang, &s, &c);
        float x0 = row[e]     * scale * g[e];
        float x1 = row[e + 1] * scale * g[e + 1];
        row[e]     = x0 * c - x1 * s;
        row[e + 1] = x0 * s + x1 * c;
    }
}

// ---------------- causal flash attention (fp32) ----------------
__global__ __launch_bounds__(256) void flash_attn(const float* __restrict__ Q,
                                                  const float* __restrict__ K,
                                                  const float* __restrict__ V,
                                                  float* __restrict__ O)
{
    extern __shared__ float sm[];
    float* Qs   = sm;
    float* KVs  = Qs + 128 * 65;
    float* Ss   = KVs + 128 * 65;
    float* mnew = Ss + 64 * 65;
    float* fac  = mnew + 64;
    float* lsh  = fac + 64;

    const int qt = blockIdx.x;
    const int h  = blockIdx.y;
    const int q0 = qt * 64;
    const int tid = threadIdx.x;
    const int tr = tid >> 4;
    const int tc = tid & 15;
    const float scale = 0.08838834764831845f;

    for (int idx = tid; idx < 64 * 128; idx += 256) {
        int r = idx >> 7, i = idx & 127;
        Qs[i * 65 + r] = Q[(size_t)(q0 + r) * DIM + h * HD + i];
    }

    float o[4][8];
#pragma unroll
    for (int a = 0; a < 4; a++)
#pragma unroll
        for (int d = 0; d < 8; d++) o[a][d] = 0.f;

    float mrow = -INFINITY;
    float lrow = 0.f;

    for (int j = 0; j <= qt; j++) {
        for (int idx = tid; idx < 64 * 128; idx += 256) {
            int c = idx >> 7, i = idx & 127;
            KVs[i * 65 + c] = K[(size_t)(j * 64 + c) * DIM + h * HD + i];
        }
        __syncthreads();

        float acc[4][4];
#pragma unroll
        for (int a = 0; a < 4; a++)
#pragma unroll
            for (int b = 0; b < 4; b++) acc[a][b] = 0.f;

#pragma unroll 4
        for (int i = 0; i < 128; i++) {
            float qv[4], kv[4];
#pragma unroll
            for (int a = 0; a < 4; a++) qv[a] = Qs[i * 65 + 4 * tr + a];
#pragma unroll
            for (int b = 0; b < 4; b++) kv[b] = KVs[i * 65 + 4 * tc + b];
#pragma unroll
            for (int a = 0; a < 4; a++)
#pragma unroll
                for (int b = 0; b < 4; b++) acc[a][b] += qv[a] * kv[b];
        }

        const bool diag = (j == qt);
#pragma unroll
        for (int a = 0; a < 4; a++)
#pragma unroll
            for (int b = 0; b < 4; b++) {
                float s = acc[a][b] * scale;
                if (diag && (4 * tc + b) > (4 * tr + a)) s = -1e30f;
                Ss[(4 * tr + a) * 65 + 4 * tc + b] = s;
            }
        __syncthreads();

        if (tid < 64) {
            float mx = -1e30f;
#pragma unroll 8
            for (int c = 0; c < 64; c++) mx = fmaxf(mx, Ss[tid * 65 + c]);
            float mn = fmaxf(mrow, mx);
            fac[tid]  = (mrow == -INFINITY) ? 0.f : __expf(mrow - mn);
            mnew[tid] = mn;
            mrow = mn;
        }
        __syncthreads();

        for (int idx = tid; idx < 64 * 64; idx += 256) {
            int r = idx >> 6, c = idx & 63;
            Ss[r * 65 + c] = __expf(Ss[r * 65 + c] - mnew[r]);
        }
        for (int idx = tid; idx < 64 * 128; idx += 256) {
            int k = idx >> 7, d = idx & 127;
            KVs[k * 128 + d] = V[(size_t)(j * 64 + k) * DIM + h * HD + d];
        }
        {
            float f[4];
#pragma unroll
            for (int a = 0; a < 4; a++) f[a] = fac[4 * tr + a];
#pragma unroll
            for (int a = 0; a < 4; a++)
#pragma unroll
                for (int d = 0; d < 8; d++) o[a][d] *= f[a];
        }
        __syncthreads();

        if (tid < 64) {
            float rs = 0.f;
#pragma unroll 8
            for (int c = 0; c < 64; c++) rs += Ss[tid * 65 + c];
            lrow = lrow * fac[tid] + rs;
        }

#pragma unroll 4
        for (int k = 0; k < 64; k++) {
            float pv[4], vv[8];
#pragma unroll
            for (int a = 0; a < 4; a++) pv[a] = Ss[(4 * tr + a) * 65 + k];
#pragma unroll
            for (int d = 0; d < 8; d++) vv[d] = KVs[k * 128 + tc * 8 + d];
#pragma unroll
            for (int a = 0; a < 4; a++)
#pragma unroll
                for (int d = 0; d < 8; d++) o[a][d] += pv[a] * vv[d];
        }
        __syncthreads();
    }

    if (tid < 64) lsh[tid] = lrow;
    __syncthreads();

#pragma unroll
    for (int a = 0; a < 4; a++) {
        float inv = 1.f / lsh[4 * tr + a];
        float* op = O + (size_t)(q0 + 4 * tr + a) * DIM + h * HD + tc * 8;
        float4 v0, v1;
        v0.x = o[a][0] * inv; v0.y = o[a][1] * inv;
        v0.z = o[a][2] * inv; v0.w = o[a][3] * inv;
        v1.x = o[a][4] * inv; v1.y = o[a][5] * inv;
        v1.z = o[a][6] * inv; v1.w = o[a][7] * inv;
        *(float4*)op       = v0;
        *(float4*)(op + 4) = v1;
    }
}

// ---------------- launch ----------------
extern "C" void kernel_launch(void* const* d_in, const int* in_sizes, int n_in,
                              void* d_out, int out_size)
{
    (void)in_sizes; (void)n_in; (void)out_size;
    const float* x     = (const float*)d_in[0];
    const float* freqs = (const float*)d_in[1];
    const float* Wq    = (const float*)d_in[2];
    const float* bq    = (const float*)d_in[3];
    const float* Wk    = (const float*)d_in[4];
    const float* bk    = (const float*)d_in[5];
    const float* Wv    = (const float*)d_in[6];
    const float* bv    = (const float*)d_in[7];
    const float* Wo    = (const float*)d_in[8];
    const float* bo    = (const float*)d_in[9];
    const float* gq    = (const float*)d_in[10];
    const float* gk    = (const float*)d_in[11];

    float *q, *k, *v, *o;
    cudaGetSymbolAddress((void**)&q, g_q);
    cudaGetSymbolAddress((void**)&k, g_k);
    cudaGetSymbolAddress((void**)&v, g_v);
    cudaGetSymbolAddress((void**)&o, g_o);

    const int gsm = NSTG * STG_BYTES;  // 56832 bytes
    cudaFuncSetAttribute(gemm_mma, cudaFuncAttributeMaxDynamicSharedMemorySize, gsm);

    dim3 ggrid(DIM / 128, T_SEQ / 128);  // (16, 32)
    gemm_mma<<<ggrid, 256, gsm>>>(x, Wq, bq, q);
    gemm_mma<<<ggrid, 256, gsm>>>(x, Wk, bk, k);
    gemm_mma<<<ggrid, 256, gsm>>>(x, Wv, bv, v);

    rmsnorm_rope<<<T_SEQ, 256>>>(q, gq, freqs);
    rmsnorm_rope<<<T_SEQ, 256>>>(k, gk, freqs);

    const int smem_bytes = (128 * 65 + 128 * 65 + 64 * 65 + 3 * 64) * (int)sizeof(float);
    cudaFuncSetAttribute(flash_attn, cudaFuncAttributeMaxDynamicSharedMemorySize, smem_bytes);
    dim3 agrid(T_SEQ / 64, NH);
    flash_attn<<<agrid, 256, smem_bytes>>>(q, k, v, o);

    gemm_mma<<<ggrid, 256, gsm>>>(o, Wo, bo, (float*)d_out);
}

// round 5
// speedup vs baseline: 3.5309x; 2.3000x over previous
#include <cuda_runtime.h>
#include <math.h>
#include <stdint.h>

#define T_SEQ 4096
#define DIM   2048
#define NH    16
#define HD    128
#define GK    2048

// ---------------- scratch (no allocations allowed) ----------------
__device__ float g_q[T_SEQ * DIM];
__device__ float g_k[T_SEQ * DIM];
__device__ float g_v[T_SEQ * DIM];
__device__ float g_o[T_SEQ * DIM];
__device__ float g_kt[DIM * T_SEQ];   // K transposed per head: [h][d][t]

// =================== helpers ===================
__device__ __forceinline__ uint32_t smem_u32(const void* p) {
    uint32_t a;
    asm("{ .reg .u64 t; cvta.to.shared.u64 t, %1; cvt.u32.u64 %0, t; }" : "=r"(a) : "l"(p));
    return a;
}
__device__ __forceinline__ uint32_t tf32b(float x) {
    uint32_t r;
    asm("cvt.rna.tf32.f32 %0, %1;" : "=r"(r) : "f"(x));
    return r;
}
__device__ __forceinline__ float tf32f(float x) { return __uint_as_float(tf32b(x)); }
__device__ __forceinline__ void cpa16(uint32_t saddr, const void* g) {
    asm volatile("cp.async.cg.shared.global [%0], [%1], 16;" :: "r"(saddr), "l"(g));
}
__device__ __forceinline__ void mma8(float* d, const uint32_t* a, uint32_t b0, uint32_t b1) {
    asm volatile(
        "mma.sync.aligned.m16n8k8.row.col.f32.tf32.tf32.f32 "
        "{%0,%1,%2,%3}, {%4,%5,%6,%7}, {%8,%9}, {%0,%1,%2,%3};"
        : "+f"(d[0]), "+f"(d[1]), "+f"(d[2]), "+f"(d[3])
        : "r"(a[0]), "r"(a[1]), "r"(a[2]), "r"(a[3]), "r"(b0), "r"(b1));
}

// =================== mma.sync tf32 GEMM (from R4, + optional tf32-rounded output) ===================
#define BK        16
#define NSTG      3
#define A_ROWB    80
#define B_ROWB    544
#define A_BYTES   (128 * A_ROWB)
#define B_BYTES   (BK * B_ROWB)
#define STG_BYTES (A_BYTES + B_BYTES)
#define NT        (GK / BK)

__device__ __forceinline__ void load_stage(uint32_t sb, const float* __restrict__ A,
                                           const float* __restrict__ W,
                                           int m0, int n0, int kt, int tid) {
    uint32_t st = sb + (uint32_t)(kt % NSTG) * STG_BYTES;
    const int k0 = kt * BK;
#pragma unroll
    for (int i = 0; i < 2; i++) {
        int id = tid + i * 256;
        int row = id >> 2, seg = id & 3;
        cpa16(st + row * A_ROWB + seg * 16,
              A + (size_t)(m0 + row) * GK + k0 + seg * 4);
    }
#pragma unroll
    for (int i = 0; i < 2; i++) {
        int id = tid + i * 256;
        int kr = id >> 5, seg = id & 31;
        cpa16(st + A_BYTES + kr * B_ROWB + seg * 16,
              W + (size_t)(k0 + kr) * DIM + n0 + seg * 4);
    }
}

__global__ __launch_bounds__(256) void gemm_mma(const float* __restrict__ A,
                                                const float* __restrict__ W,
                                                const float* __restrict__ bias,
                                                float* __restrict__ C,
                                                int round_out)
{
    extern __shared__ __align__(16) char smem[];
    const uint32_t sb = smem_u32(smem);
    const int tid  = threadIdx.x;
    const int lane = tid & 31;
    const int wid  = tid >> 5;
    const int wm   = (wid >> 1) * 32;
    const int wn   = (wid & 1) * 64;
    const int n0   = blockIdx.x * 128;
    const int m0   = blockIdx.y * 128;

    const int gq = lane >> 2;
    const int tg = lane & 3;

    float acc[2][8][4];
#pragma unroll
    for (int mi = 0; mi < 2; mi++)
#pragma unroll
        for (int ni = 0; ni < 8; ni++)
#pragma unroll
            for (int r = 0; r < 4; r++) acc[mi][ni][r] = 0.f;

#pragma unroll
    for (int kt = 0; kt < NSTG; kt++) {
        load_stage(sb, A, W, m0, n0, kt, tid);
        asm volatile("cp.async.commit_group;" ::: "memory");
    }

    for (int kt = 0; kt < NT; kt++) {
        asm volatile("cp.async.wait_group %0;" :: "n"(NSTG - 1) : "memory");
        __syncthreads();

        const float* smf = (const float*)(smem + (kt % NSTG) * STG_BYTES);
        const float* bsf = (const float*)(smem + (kt % NSTG) * STG_BYTES + A_BYTES);

#pragma unroll
        for (int ks = 0; ks < BK; ks += 8) {
            uint32_t afr[2][4];
#pragma unroll
            for (int mi = 0; mi < 2; mi++) {
                int r0 = wm + mi * 16 + gq;
                int c0 = ks + tg;
                afr[mi][0] = tf32b(smf[r0 * 20 + c0]);
                afr[mi][1] = tf32b(smf[(r0 + 8) * 20 + c0]);
                afr[mi][2] = tf32b(smf[r0 * 20 + c0 + 4]);
                afr[mi][3] = tf32b(smf[(r0 + 8) * 20 + c0 + 4]);
            }
#pragma unroll
            for (int ni = 0; ni < 8; ni++) {
                int nb = wn + ni * 8 + gq;
                uint32_t b0 = tf32b(bsf[(ks + tg) * 136 + nb]);
                uint32_t b1 = tf32b(bsf[(ks + tg + 4) * 136 + nb]);
                mma8(acc[0][ni], afr[0], b0, b1);
                mma8(acc[1][ni], afr[1], b0, b1);
            }
        }
        __syncthreads();

        if (kt + NSTG < NT)
            load_stage(sb, A, W, m0, n0, kt + NSTG, tid);
        asm volatile("cp.async.commit_group;" ::: "memory");
    }

#pragma unroll
    for (int mi = 0; mi < 2; mi++) {
        int row = m0 + wm + mi * 16 + gq;
#pragma unroll
        for (int ni = 0; ni < 8; ni++) {
            int col = n0 + wn + ni * 8 + 2 * tg;
            float2 bz = *(const float2*)(bias + col);
            float2 v0, v1;
            v0.x = acc[mi][ni][0] + bz.x; v0.y = acc[mi][ni][1] + bz.y;
            v1.x = acc[mi][ni][2] + bz.x; v1.y = acc[mi][ni][3] + bz.y;
            if (round_out) {
                v0.x = tf32f(v0.x); v0.y = tf32f(v0.y);
                v1.x = tf32f(v1.x); v1.y = tf32f(v1.y);
            }
            *(float2*)(C + (size_t)row * DIM + col)       = v0;
            *(float2*)(C + (size_t)(row + 8) * DIM + col) = v1;
        }
    }
}

// ---------------- RMSNorm + RoPE (optional tf32-rounded output) ----------------
__global__ __launch_bounds__(256) void rmsnorm_rope(float* __restrict__ buf,
                                                    const float* __restrict__ g,
                                                    const float* __restrict__ freqs,
                                                    int round_out)
{
    const int t = blockIdx.x;
    float* row = buf + (size_t)t * DIM;

    float ss = 0.f;
    for (int i = threadIdx.x; i < DIM; i += 256) {
        float v = row[i];
        ss += v * v;
    }
#pragma unroll
    for (int off = 16; off; off >>= 1) ss += __shfl_xor_sync(0xFFFFFFFFu, ss, off);

    __shared__ float red[8];
    __shared__ float stot;
    if ((threadIdx.x & 31) == 0) red[threadIdx.x >> 5] = ss;
    __syncthreads();
    if (threadIdx.x == 0) {
        float tot = 0.f;
#pragma unroll
        for (int i = 0; i < 8; i++) tot += red[i];
        stot = tot;
    }
    __syncthreads();

    const float scale = rsqrtf(stot * (1.f / DIM) + 1e-6f);

    for (int p = threadIdx.x; p < DIM / 2; p += 256) {
        int e   = 2 * p;
        int pin = p & 63;
        float ang = freqs[(size_t)t * 64 + pin];
        float c, s;
        sincosf(ang, &s, &c);
        float x0 = row[e]     * scale * g[e];
        float x1 = row[e + 1] * scale * g[e + 1];
        float y0 = x0 * c - x1 * s;
        float y1 = x0 * s + x1 * c;
        if (round_out) { y0 = tf32f(y0); y1 = tf32f(y1); }
        row[e]     = y0;
        row[e + 1] = y1;
    }
}

// ---------------- transpose K -> Kt[h][d][t] with tf32 rounding ----------------
__global__ __launch_bounds__(256) void transpose_k(const float* __restrict__ K,
                                                   float* __restrict__ Kt)
{
    __shared__ float t[32][33];
    const int t0 = blockIdx.x * 32;
    const int d0 = blockIdx.y * 32;
    const int tx = threadIdx.x & 31, ty = threadIdx.x >> 5;  // (32, 8)
#pragma unroll
    for (int i = 0; i < 4; i++)
        t[ty + 8 * i][tx] = K[(size_t)(t0 + ty + 8 * i) * DIM + d0 + tx];
    __syncthreads();
#pragma unroll
    for (int i = 0; i < 4; i++)
        Kt[(size_t)(d0 + ty + 8 * i) * T_SEQ + t0 + tx] = tf32f(t[tx][ty + 8 * i]);
}

// ---------------- causal flash attention via mma.sync tf32 ----------------
// CTA: 128 queries (8 warps x 16 rows), 64-key tiles, double-buffered cp.async K/V.
// Q pre-rounded tf32, Kt pre-rounded dim-major, V pre-rounded. Warp-local softmax.
#define FA_QT  128
#define FA_KT  64
#define Q_LD   132
#define KT_LD  72
#define V_LD   136
#define SM_Q   0
#define SM_KT  (FA_QT * Q_LD)                        // 16896 floats
#define SM_V   (SM_KT + 2 * HD * KT_LD)              // +18432 = 35328
#define FA_SM_FLOATS (SM_V + 2 * FA_KT * V_LD)       // +17408 = 52736
#define FA_SM_BYTES  (FA_SM_FLOATS * 4)              // 210944

__device__ __forceinline__ void fa_load_kv(uint32_t sb, const float* __restrict__ Kt,
                                           const float* __restrict__ V,
                                           int h, int j, int buf, int tid) {
    const int k0 = j * FA_KT;
    uint32_t ktb = sb + (uint32_t)(SM_KT + buf * HD * KT_LD) * 4;
    uint32_t vb  = sb + (uint32_t)(SM_V + buf * FA_KT * V_LD) * 4;
#pragma unroll
    for (int i = 0; i < 8; i++) {
        int id = tid + i * 256;              // Kt: 128 dims x 16 chunks of 4 keys
        int d = id >> 4, kc = id & 15;
        cpa16(ktb + (uint32_t)(d * KT_LD + kc * 4) * 4,
              Kt + (size_t)(h * HD + d) * T_SEQ + k0 + kc * 4);
    }
#pragma unroll
    for (int i = 0; i < 8; i++) {
        int id = tid + i * 256;              // V: 64 keys x 32 chunks of 4 dims
        int key = id >> 5, c = id & 31;
        cpa16(vb + (uint32_t)(key * V_LD + c * 4) * 4,
              V + (size_t)(k0 + key) * DIM + h * HD + c * 4);
    }
}

__global__ __launch_bounds__(256) void flash_mma(const float* __restrict__ Q,
                                                 const float* __restrict__ Kt,
                                                 const float* __restrict__ V,
                                                 float* __restrict__ O)
{
    extern __shared__ float sm[];
    const uint32_t sb = smem_u32(sm);
    const int qt = gridDim.x - 1 - blockIdx.x;   // big tiles first (wave balance)
    const int h  = blockIdx.y;
    const int q0 = qt * FA_QT;
    const int tid  = threadIdx.x;
    const int lane = tid & 31, wid = tid >> 5;
    const int gq = lane >> 2, tg = lane & 3;
    const int wrow = wid * 16;
    const int nkt = 2 * qt + 2;
    const float scale = 0.08838834764831845f;

    // load Q tile into smem (already tf32-rounded)
    for (int idx = tid; idx < FA_QT * 32; idx += 256) {
        int r = idx >> 5, c4 = (idx & 31) * 4;
        float4 v = *(const float4*)(Q + (size_t)(q0 + r) * DIM + h * HD + c4);
        float* dst = sm + SM_Q + r * Q_LD + c4;
        dst[0] = v.x; dst[1] = v.y; dst[2] = v.z; dst[3] = v.w;
    }

    fa_load_kv(sb, Kt, V, h, 0, 0, tid);
    asm volatile("cp.async.commit_group;" ::: "memory");

    float oacc[16][4];
#pragma unroll
    for (int nt = 0; nt < 16; nt++)
#pragma unroll
        for (int r = 0; r < 4; r++) oacc[nt][r] = 0.f;

    float m0 = -1e30f, m1 = -1e30f, l0 = 0.f, l1 = 0.f;
    const int r0 = q0 + wrow + gq, r1 = r0 + 8;
    const float* Qp  = sm + SM_Q + (wrow + gq) * Q_LD;
    const float* Qp8 = Qp + 8 * Q_LD;

    for (int j = 0; j < nkt; j++) {
        if (j + 1 < nkt)
            fa_load_kv(sb, Kt, V, h, j + 1, (j + 1) & 1, tid);
        asm volatile("cp.async.commit_group;" ::: "memory");
        asm volatile("cp.async.wait_group 1;" ::: "memory");
        __syncthreads();

        const int buf = j & 1;
        const int k0 = j * FA_KT;
        const float* Kp = sm + SM_KT + buf * HD * KT_LD;
        const float* Vp = sm + SM_V + buf * FA_KT * V_LD;

        // ---- S = Q K^T : warp computes 16 x 64 ----
        float sacc[8][4];
#pragma unroll
        for (int nt = 0; nt < 8; nt++)
#pragma unroll
            for (int r = 0; r < 4; r++) sacc[nt][r] = 0.f;

#pragma unroll
        for (int ks = 0; ks < 16; ks++) {
            uint32_t a[4];
            a[0] = __float_as_uint(Qp [ks * 8 + tg]);
            a[1] = __float_as_uint(Qp8[ks * 8 + tg]);
            a[2] = __float_as_uint(Qp [ks * 8 + tg + 4]);
            a[3] = __float_as_uint(Qp8[ks * 8 + tg + 4]);
#pragma unroll
            for (int nt = 0; nt < 8; nt++) {
                uint32_t b0 = __float_as_uint(Kp[(ks * 8 + tg) * KT_LD + nt * 8 + gq]);
                uint32_t b1 = __float_as_uint(Kp[(ks * 8 + tg + 4) * KT_LD + nt * 8 + gq]);
                mma8(sacc[nt], a, b0, b1);
            }
        }

        // ---- scale + causal mask + row max ----
        const bool diag = (k0 + FA_KT - 1 > q0);
        float mx0 = -1e30f, mx1 = -1e30f;
#pragma unroll
        for (int nt = 0; nt < 8; nt++) {
            int c0 = k0 + nt * 8 + 2 * tg;
            float s0 = sacc[nt][0] * scale, s1 = sacc[nt][1] * scale;
            float s2 = sacc[nt][2] * scale, s3 = sacc[nt][3] * scale;
            if (diag) {
                if (c0     > r0) s0 = -1e30f;
                if (c0 + 1 > r0) s1 = -1e30f;
                if (c0     > r1) s2 = -1e30f;
                if (c0 + 1 > r1) s3 = -1e30f;
            }
            mx0 = fmaxf(mx0, fmaxf(s0, s1));
            mx1 = fmaxf(mx1, fmaxf(s2, s3));
            sacc[nt][0] = s0; sacc[nt][1] = s1; sacc[nt][2] = s2; sacc[nt][3] = s3;
        }
        mx0 = fmaxf(mx0, __shfl_xor_sync(0xFFFFFFFFu, mx0, 1));
        mx0 = fmaxf(mx0, __shfl_xor_sync(0xFFFFFFFFu, mx0, 2));
        mx1 = fmaxf(mx1, __shfl_xor_sync(0xFFFFFFFFu, mx1, 1));
        mx1 = fmaxf(mx1, __shfl_xor_sync(0xFFFFFFFFu, mx1, 2));

        const float mn0 = fmaxf(m0, mx0), mn1 = fmaxf(m1, mx1);
        const float f0 = __expf(m0 - mn0), f1 = __expf(m1 - mn1);
        m0 = mn0; m1 = mn1;

        // ---- P = exp(S - m), tf32 bits stored back into sacc ----
        float rs0 = 0.f, rs1 = 0.f;
#pragma unroll
        for (int nt = 0; nt < 8; nt++) {
            float e0 = __expf(sacc[nt][0] - mn0);
            float e1 = __expf(sacc[nt][1] - mn0);
            float e2 = __expf(sacc[nt][2] - mn1);
            float e3 = __expf(sacc[nt][3] - mn1);
            rs0 += e0 + e1; rs1 += e2 + e3;
            sacc[nt][0] = __uint_as_float(tf32b(e0));
            sacc[nt][1] = __uint_as_float(tf32b(e1));
            sacc[nt][2] = __uint_as_float(tf32b(e2));
            sacc[nt][3] = __uint_as_float(tf32b(e3));
        }
        rs0 += __shfl_xor_sync(0xFFFFFFFFu, rs0, 1);
        rs0 += __shfl_xor_sync(0xFFFFFFFFu, rs0, 2);
        rs1 += __shfl_xor_sync(0xFFFFFFFFu, rs1, 1);
        rs1 += __shfl_xor_sync(0xFFFFFFFFu, rs1, 2);
        l0 = l0 * f0 + rs0;
        l1 = l1 * f1 + rs1;

#pragma unroll
        for (int nt = 0; nt < 16; nt++) {
            oacc[nt][0] *= f0; oacc[nt][1] *= f0;
            oacc[nt][2] *= f1; oacc[nt][3] *= f1;
        }

        // ---- O += P V : acc-layout -> A-frag via quad shuffles ----
        const int src0 = (lane & 28) | (tg >> 1);
        const int src2 = src0 + 2;
#pragma unroll
        for (int s = 0; s < 8; s++) {
            float w0 = __shfl_sync(0xFFFFFFFFu, sacc[s][0], src0);
            float w1 = __shfl_sync(0xFFFFFFFFu, sacc[s][1], src0);
            float w2 = __shfl_sync(0xFFFFFFFFu, sacc[s][2], src0);
            float w3 = __shfl_sync(0xFFFFFFFFu, sacc[s][3], src0);
            float w4 = __shfl_sync(0xFFFFFFFFu, sacc[s][0], src2);
            float w5 = __shfl_sync(0xFFFFFFFFu, sacc[s][1], src2);
            float w6 = __shfl_sync(0xFFFFFFFFu, sacc[s][2], src2);
            float w7 = __shfl_sync(0xFFFFFFFFu, sacc[s][3], src2);
            uint32_t af[4];
            af[0] = __float_as_uint((tg & 1) ? w1 : w0);
            af[1] = __float_as_uint((tg & 1) ? w3 : w2);
            af[2] = __float_as_uint((tg & 1) ? w5 : w4);
            af[3] = __float_as_uint((tg & 1) ? w7 : w6);
#pragma unroll
            for (int nt = 0; nt < 16; nt++) {
                uint32_t b0 = __float_as_uint(Vp[(8 * s + tg) * V_LD + nt * 8 + gq]);
                uint32_t b1 = __float_as_uint(Vp[(8 * s + tg + 4) * V_LD + nt * 8 + gq]);
                mma8(oacc[nt], af, b0, b1);
            }
        }
        __syncthreads();
    }

    const float inv0 = 1.f / l0, inv1 = 1.f / l1;
#pragma unroll
    for (int nt = 0; nt < 16; nt++) {
        int col = h * HD + nt * 8 + 2 * tg;
        float2 w0, w1;
        w0.x = oacc[nt][0] * inv0; w0.y = oacc[nt][1] * inv0;
        w1.x = oacc[nt][2] * inv1; w1.y = oacc[nt][3] * inv1;
        *(float2*)(O + (size_t)r0 * DIM + col) = w0;
        *(float2*)(O + (size_t)r1 * DIM + col) = w1;
    }
}

// ---------------- launch ----------------
extern "C" void kernel_launch(void* const* d_in, const int* in_sizes, int n_in,
                              void* d_out, int out_size)
{
    (void)in_sizes; (void)n_in; (void)out_size;
    const float* x     = (const float*)d_in[0];
    const float* freqs = (const float*)d_in[1];
    const float* Wq    = (const float*)d_in[2];
    const float* bq    = (const float*)d_in[3];
    const float* Wk    = (const float*)d_in[4];
    const float* bk    = (const float*)d_in[5];
    const float* Wv    = (const float*)d_in[6];
    const float* bv    = (const float*)d_in[7];
    const float* Wo    = (const float*)d_in[8];
    const float* bo    = (const float*)d_in[9];
    const float* gq    = (const float*)d_in[10];
    const float* gk    = (const float*)d_in[11];

    float *q, *k, *v, *o, *kt;
    cudaGetSymbolAddress((void**)&q,  g_q);
    cudaGetSymbolAddress((void**)&k,  g_k);
    cudaGetSymbolAddress((void**)&v,  g_v);
    cudaGetSymbolAddress((void**)&o,  g_o);
    cudaGetSymbolAddress((void**)&kt, g_kt);

    const int gsm = NSTG * STG_BYTES;
    cudaFuncSetAttribute(gemm_mma, cudaFuncAttributeMaxDynamicSharedMemorySize, gsm);
    cudaFuncSetAttribute(flash_mma, cudaFuncAttributeMaxDynamicSharedMemorySize, FA_SM_BYTES);

    dim3 ggrid(DIM / 128, T_SEQ / 128);
    gemm_mma<<<ggrid, 256, gsm>>>(x, Wq, bq, q, 0);
    gemm_mma<<<ggrid, 256, gsm>>>(x, Wk, bk, k, 0);
    gemm_mma<<<ggrid, 256, gsm>>>(x, Wv, bv, v, 1);   // v rounded for flash

    rmsnorm_rope<<<T_SEQ, 256>>>(q, gq, freqs, 1);    // q rounded for flash
    rmsnorm_rope<<<T_SEQ, 256>>>(k, gk, freqs, 0);

    transpose_k<<<dim3(T_SEQ / 32, DIM / 32), 256>>>(k, kt);  // kt rounded + dim-major

    flash_mma<<<dim3(T_SEQ / FA_QT, NH), 256, FA_SM_BYTES>>>(q, kt, v, o);

    gemm_mma<<<ggrid, 256, gsm>>>(o, Wo, bo, (float*)d_out, 0);
}

// round 7
// speedup vs baseline: 3.9922x; 1.1306x over previous
#include <cuda_runtime.h>
#include <math.h>
#include <stdint.h>

#define T_SEQ 4096
#define DIM   2048
#define NH    16
#define HD    128
#define GK    2048

// ---------------- scratch (no allocations allowed) ----------------
__device__ float g_q[T_SEQ * DIM];
__device__ float g_k[T_SEQ * DIM];
__device__ float g_v[T_SEQ * DIM];
__device__ float g_o[T_SEQ * DIM];
__device__ float g_kt[DIM * T_SEQ];       // K transposed per head: [h][d][t]
__device__ float g_xr[T_SEQ * DIM];       // tf32-rounded x
__device__ float g_w[4 * DIM * DIM];      // tf32-rounded Wq,Wk,Wv,Wo

// =================== helpers ===================
__device__ __forceinline__ uint32_t smem_u32(const void* p) {
    uint32_t a;
    asm("{ .reg .u64 t; cvta.to.shared.u64 t, %1; cvt.u32.u64 %0, t; }" : "=r"(a) : "l"(p));
    return a;
}
__device__ __forceinline__ uint32_t tf32b(float x) {
    uint32_t r;
    asm("cvt.rna.tf32.f32 %0, %1;" : "=r"(r) : "f"(x));
    return r;
}
__device__ __forceinline__ float tf32f(float x) { return __uint_as_float(tf32b(x)); }
__device__ __forceinline__ void cpa16(uint32_t saddr, const void* g) {
    asm volatile("cp.async.cg.shared.global [%0], [%1], 16;" :: "r"(saddr), "l"(g));
}
__device__ __forceinline__ void mma8(float* d, const uint32_t* a, uint32_t b0, uint32_t b1) {
    asm volatile(
        "mma.sync.aligned.m16n8k8.row.col.f32.tf32.tf32.f32 "
        "{%0,%1,%2,%3}, {%4,%5,%6,%7}, {%8,%9}, {%0,%1,%2,%3};"
        : "+f"(d[0]), "+f"(d[1]), "+f"(d[2]), "+f"(d[3])
        : "r"(a[0]), "r"(a[1]), "r"(a[2]), "r"(a[3]), "r"(b0), "r"(b1));
}

// =================== tf32 round-copy ===================
__global__ __launch_bounds__(256) void round_copy(const float* __restrict__ src,
                                                  float* __restrict__ dst, int n4)
{
    int i = blockIdx.x * 256 + threadIdx.x;
    if (i < n4) {
        float4 v = ((const float4*)src)[i];
        v.x = tf32f(v.x); v.y = tf32f(v.y); v.z = tf32f(v.z); v.w = tf32f(v.w);
        ((float4*)dst)[i] = v;
    }
}

// =================== mma.sync tf32 GEMM (pre-rounded operands, no inner cvt) ===================
// grid.z selects weight slab / bias / output. z==2 output is tf32-rounded (V feeds flash).
#define BK        16
#define NSTG      3
#define A_ROWB    80
#define B_ROWB    544
#define A_BYTES   (128 * A_ROWB)
#define B_BYTES   (BK * B_ROWB)
#define STG_BYTES (A_BYTES + B_BYTES)
#define NT        (GK / BK)

__device__ __forceinline__ void load_stage(uint32_t sb, const float* __restrict__ A,
                                           const float* __restrict__ W,
                                           int m0, int n0, int kt, int tid) {
    uint32_t st = sb + (uint32_t)(kt % NSTG) * STG_BYTES;
    const int k0 = kt * BK;
#pragma unroll
    for (int i = 0; i < 2; i++) {
        int id = tid + i * 256;
        int row = id >> 2, seg = id & 3;
        cpa16(st + row * A_ROWB + seg * 16,
              A + (size_t)(m0 + row) * GK + k0 + seg * 4);
    }
#pragma unroll
    for (int i = 0; i < 2; i++) {
        int id = tid + i * 256;
        int kr = id >> 5, seg = id & 31;
        cpa16(st + A_BYTES + kr * B_ROWB + seg * 16,
              W + (size_t)(k0 + kr) * DIM + n0 + seg * 4);
    }
}

__global__ __launch_bounds__(256) void gemm_mma(const float* __restrict__ A,
                                                const float* __restrict__ Wr,
                                                const float* __restrict__ b0p,
                                                const float* __restrict__ b1p,
                                                const float* __restrict__ b2p,
                                                float* __restrict__ C0,
                                                float* __restrict__ C1,
                                                float* __restrict__ C2)
{
    extern __shared__ __align__(16) char smem[];
    const uint32_t sb = smem_u32(smem);
    const int z = blockIdx.z;
    const float* W    = Wr + (size_t)z * DIM * DIM;
    const float* bias = (z == 0) ? b0p : (z == 1) ? b1p : b2p;
    float* C          = (z == 0) ? C0  : (z == 1) ? C1  : C2;
    const int round_out = (z == 2);

    const int tid  = threadIdx.x;
    const int lane = tid & 31;
    const int wid  = tid >> 5;
    const int wm   = (wid >> 1) * 32;
    const int wn   = (wid & 1) * 64;
    const int n0   = blockIdx.x * 128;
    const int m0   = blockIdx.y * 128;

    const int gq = lane >> 2;
    const int tg = lane & 3;

    float acc[2][8][4];
#pragma unroll
    for (int mi = 0; mi < 2; mi++)
#pragma unroll
        for (int ni = 0; ni < 8; ni++)
#pragma unroll
            for (int r = 0; r < 4; r++) acc[mi][ni][r] = 0.f;

#pragma unroll
    for (int kt = 0; kt < NSTG; kt++) {
        load_stage(sb, A, W, m0, n0, kt, tid);
        asm volatile("cp.async.commit_group;" ::: "memory");
    }

    for (int kt = 0; kt < NT; kt++) {
        asm volatile("cp.async.wait_group %0;" :: "n"(NSTG - 1) : "memory");
        __syncthreads();

        const float* smf = (const float*)(smem + (kt % NSTG) * STG_BYTES);
        const float* bsf = (const float*)(smem + (kt % NSTG) * STG_BYTES + A_BYTES);

#pragma unroll
        for (int ks = 0; ks < BK; ks += 8) {
            uint32_t afr[2][4];
#pragma unroll
            for (int mi = 0; mi < 2; mi++) {
                int r0 = wm + mi * 16 + gq;
                int c0 = ks + tg;
                afr[mi][0] = __float_as_uint(smf[r0 * 20 + c0]);
                afr[mi][1] = __float_as_uint(smf[(r0 + 8) * 20 + c0]);
                afr[mi][2] = __float_as_uint(smf[r0 * 20 + c0 + 4]);
                afr[mi][3] = __float_as_uint(smf[(r0 + 8) * 20 + c0 + 4]);
            }
#pragma unroll
            for (int ni = 0; ni < 8; ni++) {
                int nb = wn + ni * 8 + gq;
                uint32_t b0 = __float_as_uint(bsf[(ks + tg) * 136 + nb]);
                uint32_t b1 = __float_as_uint(bsf[(ks + tg + 4) * 136 + nb]);
                mma8(acc[0][ni], afr[0], b0, b1);
                mma8(acc[1][ni], afr[1], b0, b1);
            }
        }
        __syncthreads();

        if (kt + NSTG < NT)
            load_stage(sb, A, W, m0, n0, kt + NSTG, tid);
        asm volatile("cp.async.commit_group;" ::: "memory");
    }

#pragma unroll
    for (int mi = 0; mi < 2; mi++) {
        int row = m0 + wm + mi * 16 + gq;
#pragma unroll
        for (int ni = 0; ni < 8; ni++) {
            int col = n0 + wn + ni * 8 + 2 * tg;
            float2 bz = *(const float2*)(bias + col);
            float2 v0, v1;
            v0.x = acc[mi][ni][0] + bz.x; v0.y = acc[mi][ni][1] + bz.y;
            v1.x = acc[mi][ni][2] + bz.x; v1.y = acc[mi][ni][3] + bz.y;
            if (round_out) {
                v0.x = tf32f(v0.x); v0.y = tf32f(v0.y);
                v1.x = tf32f(v1.x); v1.y = tf32f(v1.y);
            }
            *(float2*)(C + (size_t)row * DIM + col)       = v0;
            *(float2*)(C + (size_t)(row + 8) * DIM + col) = v1;
        }
    }
}

// ---------------- RMSNorm + RoPE (optional tf32-rounded output) ----------------
__global__ __launch_bounds__(256) void rmsnorm_rope(float* __restrict__ buf,
                                                    const float* __restrict__ g,
                                                    const float* __restrict__ freqs,
                                                    int round_out)
{
    const int t = blockIdx.x;
    float* row = buf + (size_t)t * DIM;

    float ss = 0.f;
    for (int i = threadIdx.x; i < DIM; i += 256) {
        float v = row[i];
        ss += v * v;
    }
#pragma unroll
    for (int off = 16; off; off >>= 1) ss += __shfl_xor_sync(0xFFFFFFFFu, ss, off);

    __shared__ float red[8];
    __shared__ float stot;
    if ((threadIdx.x & 31) == 0) red[threadIdx.x >> 5] = ss;
    __syncthreads();
    if (threadIdx.x == 0) {
        float tot = 0.f;
#pragma unroll
        for (int i = 0; i < 8; i++) tot += red[i];
        stot = tot;
    }
    __syncthreads();

    const float scale = rsqrtf(stot * (1.f / DIM) + 1e-6f);

    for (int p = threadIdx.x; p < DIM / 2; p += 256) {
        int e   = 2 * p;
        int pin = p & 63;
        float ang = freqs[(size_t)t * 64 + pin];
        float c, s;
        sincosf(ang, &s, &c);
        float x0 = row[e]     * scale * g[e];
        float x1 = row[e + 1] * scale * g[e + 1];
        float y0 = x0 * c - x1 * s;
        float y1 = x0 * s + x1 * c;
        if (round_out) { y0 = tf32f(y0); y1 = tf32f(y1); }
        row[e]     = y0;
        row[e + 1] = y1;
    }
}

// ---------------- transpose K -> Kt[h][d][t] with tf32 rounding ----------------
__global__ __launch_bounds__(256) void transpose_k(const float* __restrict__ K,
                                                   float* __restrict__ Kt)
{
    __shared__ float t[32][33];
    const int t0 = blockIdx.x * 32;
    const int d0 = blockIdx.y * 32;
    const int tx = threadIdx.x & 31, ty = threadIdx.x >> 5;
#pragma unroll
    for (int i = 0; i < 4; i++)
        t[ty + 8 * i][tx] = K[(size_t)(t0 + ty + 8 * i) * DIM + d0 + tx];
    __syncthreads();
#pragma unroll
    for (int i = 0; i < 4; i++)
        Kt[(size_t)(d0 + ty + 8 * i) * T_SEQ + t0 + tx] = tf32f(t[tx][ty + 8 * i]);
}

// ---------------- causal flash attention via mma.sync tf32 ----------------
// CTA: 128 queries (8 warps x 16 rows), 64-key tiles, double-buffered cp.async K/V.
// Q fragments hoisted to registers. Output tf32-rounded (feeds Wo GEMM).
#define FA_QT  128
#define FA_KT  64
#define Q_LD   132
#define KT_LD  72
#define V_LD   136
#define SM_Q   0
#define SM_KT  (FA_QT * Q_LD)
#define SM_V   (SM_KT + 2 * HD * KT_LD)
#define FA_SM_FLOATS (SM_V + 2 * FA_KT * V_LD)
#define FA_SM_BYTES  (FA_SM_FLOATS * 4)

__device__ __forceinline__ void fa_load_kv(uint32_t sb, const float* __restrict__ Kt,
                                           const float* __restrict__ V,
                                           int h, int j, int buf, int tid) {
    const int k0 = j * FA_KT;
    uint32_t ktb = sb + (uint32_t)(SM_KT + buf * HD * KT_LD) * 4;
    uint32_t vb  = sb + (uint32_t)(SM_V + buf * FA_KT * V_LD) * 4;
#pragma unroll
    for (int i = 0; i < 8; i++) {
        int id = tid + i * 256;
        int d = id >> 4, kc = id & 15;
        cpa16(ktb + (uint32_t)(d * KT_LD + kc * 4) * 4,
              Kt + (size_t)(h * HD + d) * T_SEQ + k0 + kc * 4);
    }
#pragma unroll
    for (int i = 0; i < 8; i++) {
        int id = tid + i * 256;
        int key = id >> 5, c = id & 31;
        cpa16(vb + (uint32_t)(key * V_LD + c * 4) * 4,
              V + (size_t)(k0 + key) * DIM + h * HD + c * 4);
    }
}

__global__ __launch_bounds__(256) void flash_mma(const float* __restrict__ Q,
                                                 const float* __restrict__ Kt,
                                                 const float* __restrict__ V,
                                                 float* __restrict__ O)
{
    extern __shared__ float sm[];
    const uint32_t sb = smem_u32(sm);
    const int qt = gridDim.x - 1 - blockIdx.x;
    const int h  = blockIdx.y;
    const int q0 = qt * FA_QT;
    const int tid  = threadIdx.x;
    const int lane = tid & 31, wid = tid >> 5;
    const int gq = lane >> 2, tg = lane & 3;
    const int wrow = wid * 16;
    const int nkt = 2 * qt + 2;
    const float scale = 0.08838834764831845f;

    for (int idx = tid; idx < FA_QT * 32; idx += 256) {
        int r = idx >> 5, c4 = (idx & 31) * 4;
        float4 v = *(const float4*)(Q + (size_t)(q0 + r) * DIM + h * HD + c4);
        float* dst = sm + SM_Q + r * Q_LD + c4;
        dst[0] = v.x; dst[1] = v.y; dst[2] = v.z; dst[3] = v.w;
    }

    fa_load_kv(sb, Kt, V, h, 0, 0, tid);
    asm volatile("cp.async.commit_group;" ::: "memory");
    __syncthreads();

    // hoist Q fragments to registers (reused by every key tile)
    const float* Qp  = sm + SM_Q + (wrow + gq) * Q_LD;
    const float* Qp8 = Qp + 8 * Q_LD;
    uint32_t qfr[16][4];
#pragma unroll
    for (int ks = 0; ks < 16; ks++) {
        qfr[ks][0] = __float_as_uint(Qp [ks * 8 + tg]);
        qfr[ks][1] = __float_as_uint(Qp8[ks * 8 + tg]);
        qfr[ks][2] = __float_as_uint(Qp [ks * 8 + tg + 4]);
        qfr[ks][3] = __float_as_uint(Qp8[ks * 8 + tg + 4]);
    }

    float oacc[16][4];
#pragma unroll
    for (int nt = 0; nt < 16; nt++)
#pragma unroll
        for (int r = 0; r < 4; r++) oacc[nt][r] = 0.f;

    float m0 = -1e30f, m1 = -1e30f, l0 = 0.f, l1 = 0.f;
    const int r0 = q0 + wrow + gq, r1 = r0 + 8;

    for (int j = 0; j < nkt; j++) {
        if (j + 1 < nkt)
            fa_load_kv(sb, Kt, V, h, j + 1, (j + 1) & 1, tid);
        asm volatile("cp.async.commit_group;" ::: "memory");
        asm volatile("cp.async.wait_group 1;" ::: "memory");
        __syncthreads();

        const int buf = j & 1;
        const int k0 = j * FA_KT;
        const float* Kp = sm + SM_KT + buf * HD * KT_LD;
        const float* Vp = sm + SM_V + buf * FA_KT * V_LD;

        float sacc[8][4];
#pragma unroll
        for (int nt = 0; nt < 8; nt++)
#pragma unroll
            for (int r = 0; r < 4; r++) sacc[nt][r] = 0.f;

#pragma unroll
        for (int ks = 0; ks < 16; ks++) {
#pragma unroll
            for (int nt = 0; nt < 8; nt++) {
                uint32_t b0 = __float_as_uint(Kp[(ks * 8 + tg) * KT_LD + nt * 8 + gq]);
                uint32_t b1 = __float_as_uint(Kp[(ks * 8 + tg + 4) * KT_LD + nt * 8 + gq]);
                mma8(sacc[nt], qfr[ks], b0, b1);
            }
        }

        const bool diag = (k0 + FA_KT - 1 > q0);
        float mx0 = -1e30f, mx1 = -1e30f;
#pragma unroll
        for (int nt = 0; nt < 8; nt++) {
            int c0 = k0 + nt * 8 + 2 * tg;
            float s0 = sacc[nt][0] * scale, s1 = sacc[nt][1] * scale;
            float s2 = sacc[nt][2] * scale, s3 = sacc[nt][3] * scale;
            if (diag) {
                if (c0     > r0) s0 = -1e30f;
                if (c0 + 1 > r0) s1 = -1e30f;
                if (c0     > r1) s2 = -1e30f;
                if (c0 + 1 > r1) s3 = -1e30f;
            }
            mx0 = fmaxf(mx0, fmaxf(s0, s1));
            mx1 = fmaxf(mx1, fmaxf(s2, s3));
            sacc[nt][0] = s0; sacc[nt][1] = s1; sacc[nt][2] = s2; sacc[nt][3] = s3;
        }
        mx0 = fmaxf(mx0, __shfl_xor_sync(0xFFFFFFFFu, mx0, 1));
        mx0 = fmaxf(mx0, __shfl_xor_sync(0xFFFFFFFFu, mx0, 2));
        mx1 = fmaxf(mx1, __shfl_xor_sync(0xFFFFFFFFu, mx1, 1));
        mx1 = fmaxf(mx1, __shfl_xor_sync(0xFFFFFFFFu, mx1, 2));

        const float mn0 = fmaxf(m0, mx0), mn1 = fmaxf(m1, mx1);
        const float f0 = __expf(m0 - mn0), f1 = __expf(m1 - mn1);
        m0 = mn0; m1 = mn1;

        float rs0 = 0.f, rs1 = 0.f;
#pragma unroll
        for (int nt = 0; nt < 8; nt++) {
            float e0 = __expf(sacc[nt][0] - mn0);
            float e1 = __expf(sacc[nt][1] - mn0);
            float e2 = __expf(sacc[nt][2] - mn1);
            float e3 = __expf(sacc[nt][3] - mn1);
            rs0 += e0 + e1; rs1 += e2 + e3;
            sacc[nt][0] = __uint_as_float(tf32b(e0));
            sacc[nt][1] = __uint_as_float(tf32b(e1));
            sacc[nt][2] = __uint_as_float(tf32b(e2));
            sacc[nt][3] = __uint_as_float(tf32b(e3));
        }
        rs0 += __shfl_xor_sync(0xFFFFFFFFu, rs0, 1);
        rs0 += __shfl_xor_sync(0xFFFFFFFFu, rs0, 2);
        rs1 += __shfl_xor_sync(0xFFFFFFFFu, rs1, 1);
        rs1 += __shfl_xor_sync(0xFFFFFFFFu, rs1, 2);
        l0 = l0 * f0 + rs0;
        l1 = l1 * f1 + rs1;

#pragma unroll
        for (int nt = 0; nt < 16; nt++) {
            oacc[nt][0] *= f0; oacc[nt][1] *= f0;
            oacc[nt][2] *= f1; oacc[nt][3] *= f1;
        }

        const int src0 = (lane & 28) | (tg >> 1);
        const int src2 = src0 + 2;
#pragma unroll
        for (int s = 0; s < 8; s++) {
            float w0 = __shfl_sync(0xFFFFFFFFu, sacc[s][0], src0);
            float w1 = __shfl_sync(0xFFFFFFFFu, sacc[s][1], src0);
            float w2 = __shfl_sync(0xFFFFFFFFu, sacc[s][2], src0);
            float w3 = __shfl_sync(0xFFFFFFFFu, sacc[s][3], src0);
            float w4 = __shfl_sync(0xFFFFFFFFu, sacc[s][0], src2);
            float w5 = __shfl_sync(0xFFFFFFFFu, sacc[s][1], src2);
            float w6 = __shfl_sync(0xFFFFFFFFu, sacc[s][2], src2);
            float w7 = __shfl_sync(0xFFFFFFFFu, sacc[s][3], src2);
            uint32_t af[4];
            af[0] = __float_as_uint((tg & 1) ? w1 : w0);
            af[1] = __float_as_uint((tg & 1) ? w3 : w2);
            af[2] = __float_as_uint((tg & 1) ? w5 : w4);
            af[3] = __float_as_uint((tg & 1) ? w7 : w6);
#pragma unroll
            for (int nt = 0; nt < 16; nt++) {
                uint32_t b0 = __float_as_uint(Vp[(8 * s + tg) * V_LD + nt * 8 + gq]);
                uint32_t b1 = __float_as_uint(Vp[(8 * s + tg + 4) * V_LD + nt * 8 + gq]);
                mma8(oacc[nt], af, b0, b1);
            }
        }
        __syncthreads();
    }

    const float inv0 = 1.f / l0, inv1 = 1.f / l1;
#pragma unroll
    for (int nt = 0; nt < 16; nt++) {
        int col = h * HD + nt * 8 + 2 * tg;
        float2 w0, w1;
        // tf32-rounded: feeds the (now cvt-free) Wo GEMM as A operand
        w0.x = tf32f(oacc[nt][0] * inv0); w0.y = tf32f(oacc[nt][1] * inv0);
        w1.x = tf32f(oacc[nt][2] * inv1); w1.y = tf32f(oacc[nt][3] * inv1);
        *(float2*)(O + (size_t)r0 * DIM + col) = w0;
        *(float2*)(O + (size_t)r1 * DIM + col) = w1;
    }
}

// ---------------- launch ----------------
extern "C" void kernel_launch(void* const* d_in, const int* in_sizes, int n_in,
                              void* d_out, int out_size)
{
    (void)in_sizes; (void)n_in; (void)out_size;
    const float* x     = (const float*)d_in[0];
    const float* freqs = (const float*)d_in[1];
    const float* Wq    = (const float*)d_in[2];
    const float* bq    = (const float*)d_in[3];
    const float* Wk    = (const float*)d_in[4];
    const float* bk    = (const float*)d_in[5];
    const float* Wv    = (const float*)d_in[6];
    const float* bv    = (const float*)d_in[7];
    const float* Wo    = (const float*)d_in[8];
    const float* bo    = (const float*)d_in[9];
    const float* gq    = (const float*)d_in[10];
    const float* gk    = (const float*)d_in[11];

    float *q, *k, *v, *o, *kt, *xr, *w;
    cudaGetSymbolAddress((void**)&q,  g_q);
    cudaGetSymbolAddress((void**)&k,  g_k);
    cudaGetSymbolAddress((void**)&v,  g_v);
    cudaGetSymbolAddress((void**)&o,  g_o);
    cudaGetSymbolAddress((void**)&kt, g_kt);
    cudaGetSymbolAddress((void**)&xr, g_xr);
    cudaGetSymbolAddress((void**)&w,  g_w);

    const int gsm = NSTG * STG_BYTES;
    cudaFuncSetAttribute(gemm_mma, cudaFuncAttributeMaxDynamicSharedMemorySize, gsm);
    cudaFuncSetAttribute(flash_mma, cudaFuncAttributeMaxDynamicSharedMemorySize, FA_SM_BYTES);

    const int W4 = DIM * DIM / 4;     // float4 count per weight
    round_copy<<<(T_SEQ * DIM / 4 + 255) / 256, 256>>>(x, xr, T_SEQ * DIM / 4);
    round_copy<<<(W4 + 255) / 256, 256>>>(Wq, w + 0 * DIM * DIM, W4);
    round_copy<<<(W4 + 255) / 256, 256>>>(Wk, w + 1 * DIM * DIM, W4);
    round_copy<<<(W4 + 255) / 256, 256>>>(Wv, w + 2 * DIM * DIM, W4);
    round_copy<<<(W4 + 255) / 256, 256>>>(Wo, w + 3 * DIM * DIM, W4);

    // merged QKV projection (grid.z selects weight/bias/output)
    dim3 qkvgrid(DIM / 128, T_SEQ / 128, 3);
    gemm_mma<<<qkvgrid, 256, gsm>>>(xr, w, bq, bk, bv, q, k, v);

    rmsnorm_rope<<<T_SEQ, 256>>>(q, gq, freqs, 1);
    rmsnorm_rope<<<T_SEQ, 256>>>(k, gk, freqs, 0);

    transpose_k<<<dim3(T_SEQ / 32, DIM / 32), 256>>>(k, kt);

    flash_mma<<<dim3(T_SEQ / FA_QT, NH), 256, FA_SM_BYTES>>>(q, kt, v, o);

    // output projection (z==0 only)
    dim3 ogrid(DIM / 128, T_SEQ / 128, 1);
    gemm_mma<<<ogrid, 256, gsm>>>(o, w + 3 * DIM * DIM, bo, bo, bo,
                                  (float*)d_out, (float*)d_out, (float*)d_out);
}

// round 8
// speedup vs baseline: 4.4147x; 1.1058x over previous
#include <cuda_runtime.h>
#include <math.h>
#include <stdint.h>

#define T_SEQ 4096
#define DIM   2048
#define NH    16
#define HD    128
#define GK    2048

// ---------------- scratch (no allocations allowed) ----------------
__device__ float g_q[T_SEQ * DIM];
__device__ float g_k[T_SEQ * DIM];
__device__ float g_v[T_SEQ * DIM];
__device__ float g_o[T_SEQ * DIM];
__device__ float g_kp[T_SEQ * DIM];       // K rounded, d-permuted within 8-groups (key-major)
__device__ float g_vt[DIM * T_SEQ];       // V rounded, transposed [h][d][t'], t' key-permuted
__device__ float g_xr[T_SEQ * DIM];       // tf32-rounded x
__device__ float g_w[4 * DIM * DIM];      // tf32-rounded Wq,Wk,Wv,Wo

// =================== helpers ===================
__device__ __forceinline__ uint32_t smem_u32(const void* p) {
    uint32_t a;
    asm("{ .reg .u64 t; cvta.to.shared.u64 t, %1; cvt.u32.u64 %0, t; }" : "=r"(a) : "l"(p));
    return a;
}
__device__ __forceinline__ uint32_t tf32b(float x) {
    uint32_t r;
    asm("cvt.rna.tf32.f32 %0, %1;" : "=r"(r) : "f"(x));
    return r;
}
__device__ __forceinline__ float tf32f(float x) { return __uint_as_float(tf32b(x)); }
__device__ __forceinline__ void cpa16(uint32_t saddr, const void* g) {
    asm volatile("cp.async.cg.shared.global [%0], [%1], 16;" :: "r"(saddr), "l"(g));
}
__device__ __forceinline__ void mma8(float* d, const uint32_t* a, uint32_t b0, uint32_t b1) {
    asm volatile(
        "mma.sync.aligned.m16n8k8.row.col.f32.tf32.tf32.f32 "
        "{%0,%1,%2,%3}, {%4,%5,%6,%7}, {%8,%9}, {%0,%1,%2,%3};"
        : "+f"(d[0]), "+f"(d[1]), "+f"(d[2]), "+f"(d[3])
        : "r"(a[0]), "r"(a[1]), "r"(a[2]), "r"(a[3]), "r"(b0), "r"(b1));
}

// =================== tf32 round-copy ===================
__global__ __launch_bounds__(256) void round_copy(const float* __restrict__ src,
                                                  float* __restrict__ dst, int n4)
{
    int i = blockIdx.x * 256 + threadIdx.x;
    if (i < n4) {
        float4 v = ((const float4*)src)[i];
        v.x = tf32f(v.x); v.y = tf32f(v.y); v.z = tf32f(v.z); v.w = tf32f(v.w);
        ((float4*)dst)[i] = v;
    }
}

// =================== mma.sync tf32 GEMM (BK=32, pre-rounded operands) ===================
#define BK        32
#define NSTG      3
#define A_ROWB    144                 // 36 floats (32 + 4 pad)
#define B_ROWB    544                 // 136 floats (128 + 8 pad)
#define A_BYTES   (128 * A_ROWB)      // 18432
#define B_BYTES   (BK * B_ROWB)       // 17408
#define STG_BYTES (A_BYTES + B_BYTES) // 35840
#define NT        (GK / BK)           // 64

__device__ __forceinline__ void load_stage(uint32_t sb, const float* __restrict__ A,
                                           const float* __restrict__ W,
                                           int m0, int n0, int kt, int tid) {
    uint32_t st = sb + (uint32_t)(kt % NSTG) * STG_BYTES;
    const int k0 = kt * BK;
#pragma unroll
    for (int i = 0; i < 4; i++) {
        int id = tid + i * 256;            // 0..1023: A 128 rows x 8 chunks
        int row = id >> 3, seg = id & 7;
        cpa16(st + row * A_ROWB + seg * 16,
              A + (size_t)(m0 + row) * GK + k0 + seg * 4);
    }
#pragma unroll
    for (int i = 0; i < 4; i++) {
        int id = tid + i * 256;            // 0..1023: B 32 rows x 32 chunks
        int kr = id >> 5, seg = id & 31;
        cpa16(st + A_BYTES + kr * B_ROWB + seg * 16,
              W + (size_t)(k0 + kr) * DIM + n0 + seg * 4);
    }
}

__global__ __launch_bounds__(256) void gemm_mma(const float* __restrict__ A,
                                                const float* __restrict__ Wr,
                                                const float* __restrict__ b0p,
                                                const float* __restrict__ b1p,
                                                const float* __restrict__ b2p,
                                                float* __restrict__ C0,
                                                float* __restrict__ C1,
                                                float* __restrict__ C2)
{
    extern __shared__ __align__(16) char smem[];
    const uint32_t sb = smem_u32(smem);
    const int z = blockIdx.z;
    const float* W    = Wr + (size_t)z * DIM * DIM;
    const float* bias = (z == 0) ? b0p : (z == 1) ? b1p : b2p;
    float* C          = (z == 0) ? C0  : (z == 1) ? C1  : C2;

    const int tid  = threadIdx.x;
    const int lane = tid & 31;
    const int wid  = tid >> 5;
    const int wm   = (wid >> 1) * 32;
    const int wn   = (wid & 1) * 64;
    const int n0   = blockIdx.x * 128;
    const int m0   = blockIdx.y * 128;

    const int gq = lane >> 2;
    const int tg = lane & 3;

    float acc[2][8][4];
#pragma unroll
    for (int mi = 0; mi < 2; mi++)
#pragma unroll
        for (int ni = 0; ni < 8; ni++)
#pragma unroll
            for (int r = 0; r < 4; r++) acc[mi][ni][r] = 0.f;

#pragma unroll
    for (int kt = 0; kt < NSTG; kt++) {
        load_stage(sb, A, W, m0, n0, kt, tid);
        asm volatile("cp.async.commit_group;" ::: "memory");
    }

    for (int kt = 0; kt < NT; kt++) {
        asm volatile("cp.async.wait_group %0;" :: "n"(NSTG - 1) : "memory");
        __syncthreads();

        const float* smf = (const float*)(smem + (kt % NSTG) * STG_BYTES);
        const float* bsf = (const float*)(smem + (kt % NSTG) * STG_BYTES + A_BYTES);

#pragma unroll
        for (int ks = 0; ks < BK; ks += 8) {
            uint32_t afr[2][4];
#pragma unroll
            for (int mi = 0; mi < 2; mi++) {
                int r0 = wm + mi * 16 + gq;
                int c0 = ks + tg;
                afr[mi][0] = __float_as_uint(smf[r0 * 36 + c0]);
                afr[mi][1] = __float_as_uint(smf[(r0 + 8) * 36 + c0]);
                afr[mi][2] = __float_as_uint(smf[r0 * 36 + c0 + 4]);
                afr[mi][3] = __float_as_uint(smf[(r0 + 8) * 36 + c0 + 4]);
            }
#pragma unroll
            for (int ni = 0; ni < 8; ni++) {
                int nb = wn + ni * 8 + gq;
                uint32_t b0 = __float_as_uint(bsf[(ks + tg) * 136 + nb]);
                uint32_t b1 = __float_as_uint(bsf[(ks + tg + 4) * 136 + nb]);
                mma8(acc[0][ni], afr[0], b0, b1);
                mma8(acc[1][ni], afr[1], b0, b1);
            }
        }
        __syncthreads();

        if (kt + NSTG < NT)
            load_stage(sb, A, W, m0, n0, kt + NSTG, tid);
        asm volatile("cp.async.commit_group;" ::: "memory");
    }

#pragma unroll
    for (int mi = 0; mi < 2; mi++) {
        int row = m0 + wm + mi * 16 + gq;
#pragma unroll
        for (int ni = 0; ni < 8; ni++) {
            int col = n0 + wn + ni * 8 + 2 * tg;
            float2 bz = *(const float2*)(bias + col);
            float2 v0, v1;
            v0.x = acc[mi][ni][0] + bz.x; v0.y = acc[mi][ni][1] + bz.y;
            v1.x = acc[mi][ni][2] + bz.x; v1.y = acc[mi][ni][3] + bz.y;
            *(float2*)(C + (size_t)row * DIM + col)       = v0;
            *(float2*)(C + (size_t)(row + 8) * DIM + col) = v1;
        }
    }
}

// ---------------- RMSNorm + RoPE (grid.y: 0 = Q (rounded), 1 = K (raw)) ----------------
__global__ __launch_bounds__(256) void rmsnorm_rope2(float* __restrict__ qb,
                                                     float* __restrict__ kb,
                                                     const float* __restrict__ gqw,
                                                     const float* __restrict__ gkw,
                                                     const float* __restrict__ freqs)
{
    const int t = blockIdx.x;
    const int isk = blockIdx.y;
    float* row = (isk ? kb : qb) + (size_t)t * DIM;
    const float* g = isk ? gkw : gqw;

    float ss = 0.f;
    for (int i = threadIdx.x; i < DIM; i += 256) {
        float v = row[i];
        ss += v * v;
    }
#pragma unroll
    for (int off = 16; off; off >>= 1) ss += __shfl_xor_sync(0xFFFFFFFFu, ss, off);

    __shared__ float red[8];
    __shared__ float stot;
    if ((threadIdx.x & 31) == 0) red[threadIdx.x >> 5] = ss;
    __syncthreads();
    if (threadIdx.x == 0) {
        float tot = 0.f;
#pragma unroll
        for (int i = 0; i < 8; i++) tot += red[i];
        stot = tot;
    }
    __syncthreads();

    const float scale = rsqrtf(stot * (1.f / DIM) + 1e-6f);

    for (int p = threadIdx.x; p < DIM / 2; p += 256) {
        int e   = 2 * p;
        int pin = p & 63;
        float ang = freqs[(size_t)t * 64 + pin];
        float c, s;
        sincosf(ang, &s, &c);
        float x0 = row[e]     * scale * g[e];
        float x1 = row[e + 1] * scale * g[e + 1];
        float y0 = x0 * c - x1 * s;
        float y1 = x0 * s + x1 * c;
        if (!isk) { y0 = tf32f(y0); y1 = tf32f(y1); }  // Q feeds flash A-frags directly
        row[e]     = y0;
        row[e + 1] = y1;
    }
}

// ---------------- permute K columns within 8-groups (d' = 8g+2t+h <- d = 8g+t+4h) ----------------
__global__ __launch_bounds__(256) void permute_k(const float* __restrict__ K,
                                                 float* __restrict__ Kp)
{
    int idx = blockIdx.x * 256 + threadIdx.x;       // t*DIM + c'
    int t = idx >> 11;
    int c = idx & 2047;
    int r = c & 7;
    int src = (c & ~7) + (r >> 1) + ((r & 1) << 2);
    Kp[idx] = tf32f(K[(size_t)t * DIM + src]);
}

// ---------------- transpose V -> Vt[h][d][t'] with key-permutation + rounding ----------------
__global__ __launch_bounds__(256) void transpose_v(const float* __restrict__ V,
                                                   float* __restrict__ Vt)
{
    __shared__ float t[32][33];
    const int t0 = blockIdx.x * 32;
    const int d0 = blockIdx.y * 32;
    const int tx = threadIdx.x & 31, ty = threadIdx.x >> 5;
#pragma unroll
    for (int i = 0; i < 4; i++)
        t[ty + 8 * i][tx] = V[(size_t)(t0 + ty + 8 * i) * DIM + d0 + tx];
    __syncthreads();
    const int tperm = (tx & ~7) + ((tx & 7) >> 1) + ((tx & 1) << 2);
#pragma unroll
    for (int i = 0; i < 4; i++)
        Vt[(size_t)(d0 + ty + 8 * i) * T_SEQ + t0 + tx] = tf32f(t[tperm][ty + 8 * i]);
}

// ---------------- causal flash attention via mma.sync tf32 ----------------
// K smem [64 keys][136] d-permuted -> (b0,b1) = one LDS.64.
// V smem [128 d][72] key-permuted  -> (b0,b1) = one LDS.64.
#define FA_QT  128
#define FA_KT  64
#define Q_LD   132
#define K_LD   136       // == 8 mod 32 words: conflict-free LDS.64
#define V_LDW  72        // == 8 mod 32 words
#define SM_Q   0
#define SM_KT  (FA_QT * Q_LD)                        // 16896
#define K_BUF  (FA_KT * K_LD)                        // 8704
#define SM_V   (SM_KT + 2 * K_BUF)                   // 34304
#define V_BUF  (HD * V_LDW)                          // 9216
#define FA_SM_FLOATS (SM_V + 2 * V_BUF)              // 52736
#define FA_SM_BYTES  (FA_SM_FLOATS * 4)

__device__ __forceinline__ void fa_load_kv(uint32_t sb, const float* __restrict__ Kp,
                                           const float* __restrict__ Vt,
                                           int h, int j, int buf, int tid) {
    const int k0 = j * FA_KT;
    uint32_t kbb = sb + (uint32_t)(SM_KT + buf * K_BUF) * 4;
    uint32_t vbb = sb + (uint32_t)(SM_V + buf * V_BUF) * 4;
#pragma unroll
    for (int i = 0; i < 8; i++) {
        int id = tid + i * 256;              // K: 64 keys x 32 chunks
        int key = id >> 5, c = id & 31;
        cpa16(kbb + (uint32_t)(key * K_LD + c * 4) * 4,
              Kp + (size_t)(k0 + key) * DIM + h * HD + c * 4);
    }
#pragma unroll
    for (int i = 0; i < 8; i++) {
        int id = tid + i * 256;              // V: 128 d x 16 chunks
        int d = id >> 4, c = id & 15;
        cpa16(vbb + (uint32_t)(d * V_LDW + c * 4) * 4,
              Vt + (size_t)(h * HD + d) * T_SEQ + k0 + c * 4);
    }
}

__global__ __launch_bounds__(256) void flash_mma(const float* __restrict__ Q,
                                                 const float* __restrict__ Kp_g,
                                                 const float* __restrict__ Vt_g,
                                                 float* __restrict__ O)
{
    extern __shared__ float sm[];
    const uint32_t sb = smem_u32(sm);
    const int qt = gridDim.x - 1 - blockIdx.x;
    const int h  = blockIdx.y;
    const int q0 = qt * FA_QT;
    const int tid  = threadIdx.x;
    const int lane = tid & 31, wid = tid >> 5;
    const int gq = lane >> 2, tg = lane & 3;
    const int wrow = wid * 16;
    const int nkt = 2 * qt + 2;
    const float scale = 0.08838834764831845f;

    for (int idx = tid; idx < FA_QT * 32; idx += 256) {
        int r = idx >> 5, c4 = (idx & 31) * 4;
        float4 v = *(const float4*)(Q + (size_t)(q0 + r) * DIM + h * HD + c4);
        float* dst = sm + SM_Q + r * Q_LD + c4;
        dst[0] = v.x; dst[1] = v.y; dst[2] = v.z; dst[3] = v.w;
    }

    fa_load_kv(sb, Kp_g, Vt_g, h, 0, 0, tid);
    asm volatile("cp.async.commit_group;" ::: "memory");
    __syncthreads();

    // hoist Q fragments to registers
    const float* Qp  = sm + SM_Q + (wrow + gq) * Q_LD;
    const float* Qp8 = Qp + 8 * Q_LD;
    uint32_t qfr[16][4];
#pragma unroll
    for (int ks = 0; ks < 16; ks++) {
        qfr[ks][0] = __float_as_uint(Qp [ks * 8 + tg]);
        qfr[ks][1] = __float_as_uint(Qp8[ks * 8 + tg]);
        qfr[ks][2] = __float_as_uint(Qp [ks * 8 + tg + 4]);
        qfr[ks][3] = __float_as_uint(Qp8[ks * 8 + tg + 4]);
    }

    float oacc[16][4];
#pragma unroll
    for (int nt = 0; nt < 16; nt++)
#pragma unroll
        for (int r = 0; r < 4; r++) oacc[nt][r] = 0.f;

    float m0 = -1e30f, m1 = -1e30f, l0 = 0.f, l1 = 0.f;
    const int r0 = q0 + wrow + gq, r1 = r0 + 8;

    for (int j = 0; j < nkt; j++) {
        if (j + 1 < nkt)
            fa_load_kv(sb, Kp_g, Vt_g, h, j + 1, (j + 1) & 1, tid);
        asm volatile("cp.async.commit_group;" ::: "memory");
        asm volatile("cp.async.wait_group 1;" ::: "memory");
        __syncthreads();

        const int buf = j & 1;
        const int k0 = j * FA_KT;
        const float* Kpb = sm + SM_KT + buf * K_BUF;
        const float* Vpb = sm + SM_V + buf * V_BUF;

        float sacc[8][4];
#pragma unroll
        for (int nt = 0; nt < 8; nt++)
#pragma unroll
            for (int r = 0; r < 4; r++) sacc[nt][r] = 0.f;

#pragma unroll
        for (int ks = 0; ks < 16; ks++) {
#pragma unroll
            for (int nt = 0; nt < 8; nt++) {
                float2 kb = *(const float2*)(Kpb + (nt * 8 + gq) * K_LD + ks * 8 + 2 * tg);
                mma8(sacc[nt], qfr[ks], __float_as_uint(kb.x), __float_as_uint(kb.y));
            }
        }

        const bool diag = (k0 + FA_KT - 1 > q0);
        float mx0 = -1e30f, mx1 = -1e30f;
#pragma unroll
        for (int nt = 0; nt < 8; nt++) {
            int c0 = k0 + nt * 8 + 2 * tg;
            float s0 = sacc[nt][0] * scale, s1 = sacc[nt][1] * scale;
            float s2 = sacc[nt][2] * scale, s3 = sacc[nt][3] * scale;
            if (diag) {
                if (c0     > r0) s0 = -1e30f;
                if (c0 + 1 > r0) s1 = -1e30f;
                if (c0     > r1) s2 = -1e30f;
                if (c0 + 1 > r1) s3 = -1e30f;
            }
            mx0 = fmaxf(mx0, fmaxf(s0, s1));
            mx1 = fmaxf(mx1, fmaxf(s2, s3));
            sacc[nt][0] = s0; sacc[nt][1] = s1; sacc[nt][2] = s2; sacc[nt][3] = s3;
        }
        mx0 = fmaxf(mx0, __shfl_xor_sync(0xFFFFFFFFu, mx0, 1));
        mx0 = fmaxf(mx0, __shfl_xor_sync(0xFFFFFFFFu, mx0, 2));
        mx1 = fmaxf(mx1, __shfl_xor_sync(0xFFFFFFFFu, mx1, 1));
        mx1 = fmaxf(mx1, __shfl_xor_sync(0xFFFFFFFFu, mx1, 2));

        const float mn0 = fmaxf(m0, mx0), mn1 = fmaxf(m1, mx1);
        const float f0 = __expf(m0 - mn0), f1 = __expf(m1 - mn1);
        m0 = mn0; m1 = mn1;

        float rs0 = 0.f, rs1 = 0.f;
#pragma unroll
        for (int nt = 0; nt < 8; nt++) {
            float e0 = __expf(sacc[nt][0] - mn0);
            float e1 = __expf(sacc[nt][1] - mn0);
            float e2 = __expf(sacc[nt][2] - mn1);
            float e3 = __expf(sacc[nt][3] - mn1);
            rs0 += e0 + e1; rs1 += e2 + e3;
            sacc[nt][0] = __uint_as_float(tf32b(e0));
            sacc[nt][1] = __uint_as_float(tf32b(e1));
            sacc[nt][2] = __uint_as_float(tf32b(e2));
            sacc[nt][3] = __uint_as_float(tf32b(e3));
        }
        rs0 += __shfl_xor_sync(0xFFFFFFFFu, rs0, 1);
        rs0 += __shfl_xor_sync(0xFFFFFFFFu, rs0, 2);
        rs1 += __shfl_xor_sync(0xFFFFFFFFu, rs1, 1);
        rs1 += __shfl_xor_sync(0xFFFFFFFFu, rs1, 2);
        l0 = l0 * f0 + rs0;
        l1 = l1 * f1 + rs1;

#pragma unroll
        for (int nt = 0; nt < 16; nt++) {
            oacc[nt][0] *= f0; oacc[nt][1] *= f0;
            oacc[nt][2] *= f1; oacc[nt][3] *= f1;
        }

        const int src0 = (lane & 28) | (tg >> 1);
        const int src2 = src0 + 2;
#pragma unroll
        for (int s = 0; s < 8; s++) {
            float w0 = __shfl_sync(0xFFFFFFFFu, sacc[s][0], src0);
            float w1 = __shfl_sync(0xFFFFFFFFu, sacc[s][1], src0);
            float w2 = __shfl_sync(0xFFFFFFFFu, sacc[s][2], src0);
            float w3 = __shfl_sync(0xFFFFFFFFu, sacc[s][3], src0);
            float w4 = __shfl_sync(0xFFFFFFFFu, sacc[s][0], src2);
            float w5 = __shfl_sync(0xFFFFFFFFu, sacc[s][1], src2);
            float w6 = __shfl_sync(0xFFFFFFFFu, sacc[s][2], src2);
            float w7 = __shfl_sync(0xFFFFFFFFu, sacc[s][3], src2);
            uint32_t af[4];
            af[0] = __float_as_uint((tg & 1) ? w1 : w0);
            af[1] = __float_as_uint((tg & 1) ? w3 : w2);
            af[2] = __float_as_uint((tg & 1) ? w5 : w4);
            af[3] = __float_as_uint((tg & 1) ? w7 : w6);
#pragma unroll
            for (int nt = 0; nt < 16; nt++) {
                float2 vb = *(const float2*)(Vpb + (nt * 8 + gq) * V_LDW + s * 8 + 2 * tg);
                mma8(oacc[nt], af, __float_as_uint(vb.x), __float_as_uint(vb.y));
            }
        }
        __syncthreads();
    }

    const float inv0 = 1.f / l0, inv1 = 1.f / l1;
#pragma unroll
    for (int nt = 0; nt < 16; nt++) {
        int col = h * HD + nt * 8 + 2 * tg;
        float2 w0, w1;
        w0.x = tf32f(oacc[nt][0] * inv0); w0.y = tf32f(oacc[nt][1] * inv0);
        w1.x = tf32f(oacc[nt][2] * inv1); w1.y = tf32f(oacc[nt][3] * inv1);
        *(float2*)(O + (size_t)r0 * DIM + col) = w0;
        *(float2*)(O + (size_t)r1 * DIM + col) = w1;
    }
}

// ---------------- launch ----------------
extern "C" void kernel_launch(void* const* d_in, const int* in_sizes, int n_in,
                              void* d_out, int out_size)
{
    (void)in_sizes; (void)n_in; (void)out_size;
    const float* x     = (const float*)d_in[0];
    const float* freqs = (const float*)d_in[1];
    const float* Wq    = (const float*)d_in[2];
    const float* bq    = (const float*)d_in[3];
    const float* Wk    = (const float*)d_in[4];
    const float* bk    = (const float*)d_in[5];
    const float* Wv    = (const float*)d_in[6];
    const float* bv    = (const float*)d_in[7];
    const float* Wo    = (const float*)d_in[8];
    const float* bo    = (const float*)d_in[9];
    const float* gq    = (const float*)d_in[10];
    const float* gk    = (const float*)d_in[11];

    float *q, *k, *v, *o, *kp, *vt, *xr, *w;
    cudaGetSymbolAddress((void**)&q,  g_q);
    cudaGetSymbolAddress((void**)&k,  g_k);
    cudaGetSymbolAddress((void**)&v,  g_v);
    cudaGetSymbolAddress((void**)&o,  g_o);
    cudaGetSymbolAddress((void**)&kp, g_kp);
    cudaGetSymbolAddress((void**)&vt, g_vt);
    cudaGetSymbolAddress((void**)&xr, g_xr);
    cudaGetSymbolAddress((void**)&w,  g_w);

    const int gsm = NSTG * STG_BYTES;   // 107520
    cudaFuncSetAttribute(gemm_mma, cudaFuncAttributeMaxDynamicSharedMemorySize, gsm);
    cudaFuncSetAttribute(flash_mma, cudaFuncAttributeMaxDynamicSharedMemorySize, FA_SM_BYTES);

    const int W4 = DIM * DIM / 4;
    round_copy<<<(T_SEQ * DIM / 4 + 255) / 256, 256>>>(x, xr, T_SEQ * DIM / 4);
    round_copy<<<(W4 + 255) / 256, 256>>>(Wq, w + 0 * DIM * DIM, W4);
    round_copy<<<(W4 + 255) / 256, 256>>>(Wk, w + 1 * DIM * DIM, W4);
    round_copy<<<(W4 + 255) / 256, 256>>>(Wv, w + 2 * DIM * DIM, W4);
    round_copy<<<(W4 + 255) / 256, 256>>>(Wo, w + 3 * DIM * DIM, W4);

    dim3 qkvgrid(DIM / 128, T_SEQ / 128, 3);
    gemm_mma<<<qkvgrid, 256, gsm>>>(xr, w, bq, bk, bv, q, k, v);

    rmsnorm_rope2<<<dim3(T_SEQ, 2), 256>>>(q, k, gq, gk, freqs);

    permute_k<<<T_SEQ * DIM / 256, 256>>>(k, kp);
    transpose_v<<<dim3(T_SEQ / 32, DIM / 32), 256>>>(v, vt);

    flash_mma<<<dim3(T_SEQ / FA_QT, NH), 256, FA_SM_BYTES>>>(q, kp, vt, o);

    dim3 ogrid(DIM / 128, T_SEQ / 128, 1);
    gemm_mma<<<ogrid, 256, gsm>>>(o, w + 3 * DIM * DIM, bo, bo, bo,
                                  (float*)d_out, (float*)d_out, (float*)d_out);
}